// round 1
// baseline (speedup 1.0000x reference)
#include <cuda_runtime.h>
#include <cfloat>

#define Bsz 8
#define Npt 1024
#define KNN 20

// ---------------- scratch (device globals; no allocation) ----------------
__device__ float g_xx[Bsz * Npt];                       // squared norms
__device__ float g_dist[(size_t)Bsz * Npt * Npt];       // dist matrix; reused as conv5 output "e"
__device__ int   g_idx[Bsz * Npt * KNN];                // knn indices
__device__ float g_xc[(size_t)Bsz * Npt * 512];         // concat feature buffer (B,N,512): x1|x2|x3|x4
__device__ float g_Y[(size_t)Bsz * Npt * 512];          // per-layer GEMM output (B*N, 2*O)
__device__ float g_Weff[512 * 256];                     // folded weights (2O, C)
__device__ float g_poolpart[4 * Bsz * 1024];            // partial max-pool

// ---------------- squared norms ----------------
__global__ void sqnorm_kernel(const float* __restrict__ Fext, int chanoff, int lda, int C) {
    int i = blockIdx.x * 256 + threadIdx.x;   // point index 0..8191
    if (i >= Bsz * Npt) return;
    const float* p = Fext ? (Fext + (size_t)i * lda) : (g_xc + (size_t)i * 512 + chanoff);
    float acc = 0.f;
    for (int c = 0; c < C; c++) acc = fmaf(p[c], p[c], acc);
    g_xx[i] = acc;
}

// ---------------- generic tiled GEMM: C[r][c] = epi( sum_k A[r][k]*Bt[c][k] ) ----------------
// TM=128 rows, TN=64 cols, KC=16, 256 threads, 8x4 per thread.
// DIST: Bt = A (per-batch), epilogue 2*acc - xx[r] - xx[c], out -> g_dist
// else: Bt = Bext (or g_Weff), out -> (Csel==0 ? g_dist : g_Y)
template <bool DIST>
__global__ void gemm_kernel(const float* __restrict__ Aext, int Aoff, int lda, long sA,
                            const float* __restrict__ Bext, int ldb,
                            int Csel, int ldc, long sC, int Kdim) {
    __shared__ float As[16][132];
    __shared__ float Bs[16][68];

    const float* Abase = Aext ? Aext : (g_xc + Aoff);
    const float* A = Abase + (size_t)blockIdx.z * sA;
    const float* Bt;
    int ldbb;
    if (DIST) { Bt = A; ldbb = lda; }
    else      { Bt = Bext ? Bext : g_Weff; ldbb = ldb; }
    float* Cp = (Csel == 0 ? g_dist : g_Y) + (size_t)blockIdx.z * sC;

    int tid = threadIdx.x;
    int tx = tid & 15, ty = tid >> 4;
    int row0 = blockIdx.x * 128;
    int col0 = blockIdx.y * 64;

    float acc[8][4];
#pragma unroll
    for (int i = 0; i < 8; i++)
#pragma unroll
        for (int j = 0; j < 4; j++) acc[i][j] = 0.f;

    for (int k0 = 0; k0 < Kdim; k0 += 16) {
#pragma unroll
        for (int l = 0; l < 8; l++) {                 // A tile 128x16
            int i = tid + l * 256;
            int r = i >> 4, k = i & 15;
            int gk = k0 + k;
            As[k][r] = (gk < Kdim) ? A[(size_t)(row0 + r) * lda + gk] : 0.f;
        }
#pragma unroll
        for (int l = 0; l < 4; l++) {                 // B tile 64x16
            int i = tid + l * 256;
            int c = i >> 4, k = i & 15;
            int gk = k0 + k;
            Bs[k][c] = (gk < Kdim) ? Bt[(size_t)(col0 + c) * ldbb + gk] : 0.f;
        }
        __syncthreads();
#pragma unroll
        for (int k = 0; k < 16; k++) {
            float4 a0 = *(const float4*)&As[k][ty * 8];
            float4 a1 = *(const float4*)&As[k][ty * 8 + 4];
            float4 b4 = *(const float4*)&Bs[k][tx * 4];
            float av[8] = {a0.x, a0.y, a0.z, a0.w, a1.x, a1.y, a1.z, a1.w};
            float bv[4] = {b4.x, b4.y, b4.z, b4.w};
#pragma unroll
            for (int i = 0; i < 8; i++)
#pragma unroll
                for (int j = 0; j < 4; j++)
                    acc[i][j] = fmaf(av[i], bv[j], acc[i][j]);
        }
        __syncthreads();
    }

    const float* xx = g_xx + (size_t)blockIdx.z * Npt;
#pragma unroll
    for (int i = 0; i < 8; i++) {
        int r = row0 + ty * 8 + i;
#pragma unroll
        for (int j = 0; j < 4; j++) {
            int c = col0 + tx * 4 + j;
            float v = acc[i][j];
            if (DIST) v = 2.f * v - xx[r] - xx[c];
            Cp[(size_t)r * ldc + c] = v;
        }
    }
}

// ---------------- top-K (K=20) per row, jax tie-break (lower index wins) ----------------
__global__ void topk_kernel() {
    int bn = blockIdx.x;                               // b*N + n
    __shared__ float sv[Npt];
    __shared__ float wv[8];
    __shared__ int   wi[8];
    const float* row = g_dist + (size_t)bn * Npt;
    for (int i = threadIdx.x; i < Npt; i += 256) sv[i] = row[i];
    __syncthreads();
    for (int k = 0; k < KNN; k++) {
        float bv = -FLT_MAX;
        int bi = 1 << 30;
        for (int i = threadIdx.x; i < Npt; i += 256) {
            float v = sv[i];
            if (v > bv || (v == bv && i < bi)) { bv = v; bi = i; }
        }
#pragma unroll
        for (int off = 16; off; off >>= 1) {
            float ov = __shfl_down_sync(0xffffffffu, bv, off);
            int   oi = __shfl_down_sync(0xffffffffu, bi, off);
            if (ov > bv || (ov == bv && oi < bi)) { bv = ov; bi = oi; }
        }
        if ((threadIdx.x & 31) == 0) { wv[threadIdx.x >> 5] = bv; wi[threadIdx.x >> 5] = bi; }
        __syncthreads();
        if (threadIdx.x == 0) {
            for (int w = 1; w < 8; w++)
                if (wv[w] > bv || (wv[w] == bv && wi[w] < bi)) { bv = wv[w]; bi = wi[w]; }
            g_idx[bn * KNN + k] = bi;
            sv[bi] = -FLT_MAX;
        }
        __syncthreads();
    }
}

// ---------------- folded weights: Weff[0:O]=W1, Weff[O:2O]=W2-W1 ----------------
__global__ void weff_kernel(const float* __restrict__ W, int O, int C) {
    int i = blockIdx.x * 256 + threadIdx.x;
    if (i >= 2 * O * C) return;
    int j = i / C, c = i - j * C;
    float v;
    if (j < O) v = W[(size_t)j * 2 * C + c];
    else {
        int jo = j - O;
        v = W[(size_t)jo * 2 * C + C + c] - W[(size_t)jo * 2 * C + c];
    }
    g_Weff[i] = v;
}

// ---------------- gather + bias + bn + lrelu + max over K ----------------
__global__ void aggregate_kernel(int O, const float* __restrict__ bias,
                                 const float* __restrict__ bng, const float* __restrict__ bnb,
                                 int outoff) {
    int bn = blockIdx.x;
    int b = bn >> 10;
    int o = threadIdx.x;                               // blockDim == O
    __shared__ int sidx[KNN];
    if (o < KNN) sidx[o] = g_idx[bn * KNN + o];
    __syncthreads();
    int twoO = 2 * O;
    const float* Yrow = g_Y + (size_t)bn * twoO;
    float ctr = Yrow[O + o];
    if (bias) ctr += bias[o];
    float scale = bng[o] * rsqrtf(1.0f + 1e-5f);
    float shift = bnb[o];
    const float* Yb = g_Y + (size_t)(b << 10) * twoO;
    float m = -FLT_MAX;
#pragma unroll
    for (int k = 0; k < KNN; k++) {
        float v = Yb[(size_t)sidx[k] * twoO + o] + ctr;
        v = fmaf(v, scale, shift);
        v = (v >= 0.f) ? v : 0.01f * v;
        m = fmaxf(m, v);
    }
    g_xc[(size_t)bn * 512 + outoff + o] = m;
}

// ---------------- partial max-pool over N (conv5 output lives in g_dist) ----------------
__global__ void gpool_kernel() {
    int b = blockIdx.x >> 2;
    int ob = (blockIdx.x & 3) * 256;
    int chunk = blockIdx.y;                            // 0..3, 256 points each
    int o = ob + threadIdx.x;
    const float* p = g_dist + ((size_t)(b * Npt) + chunk * 256) * 1024 + o;
    float m = -FLT_MAX;
    for (int n = 0; n < 256; n++) m = fmaxf(m, p[(size_t)n * 1024]);
    g_poolpart[chunk * (Bsz * 1024) + b * 1024 + o] = m;
}

// ---------------- fused MLP head ----------------
__global__ void mlp_kernel(const float* __restrict__ lin1_w,
                           const float* __restrict__ bn6_g, const float* __restrict__ bn6_b,
                           const float* __restrict__ lin2_w, const float* __restrict__ lin2_b,
                           const float* __restrict__ bn7_g, const float* __restrict__ bn7_b,
                           const float* __restrict__ lin3_w, const float* __restrict__ lin3_b,
                           float* __restrict__ out) {
    int b = blockIdx.x, t = threadIdx.x;
    __shared__ float sy[1024];
    __shared__ float s1[512];
    __shared__ float s2[256];
    for (int i = t; i < 1024; i += 256) {
        float m = g_poolpart[b * 1024 + i];
        m = fmaxf(m, g_poolpart[8192 + b * 1024 + i]);
        m = fmaxf(m, g_poolpart[2 * 8192 + b * 1024 + i]);
        m = fmaxf(m, g_poolpart[3 * 8192 + b * 1024 + i]);
        sy[i] = m;
    }
    __syncthreads();
    const float r = rsqrtf(1.0f + 1e-5f);
    for (int j = t; j < 512; j += 256) {
        const float* w = lin1_w + (size_t)j * 1024;
        float acc = 0.f;
        for (int c = 0; c < 1024; c++) acc = fmaf(w[c], sy[c], acc);
        float v = fmaf(acc, bn6_g[j] * r, bn6_b[j]);
        s1[j] = (v >= 0.f) ? v : 0.01f * v;
    }
    __syncthreads();
    {
        const float* w = lin2_w + (size_t)t * 512;
        float acc = lin2_b[t];
        for (int c = 0; c < 512; c++) acc = fmaf(w[c], s1[c], acc);
        float v = fmaf(acc, bn7_g[t] * r, bn7_b[t]);
        s2[t] = (v >= 0.f) ? v : 0.01f * v;
    }
    __syncthreads();
    if (t < 40) {
        const float* w = lin3_w + (size_t)t * 256;
        float acc = lin3_b[t];
        for (int c = 0; c < 256; c++) acc = fmaf(w[c], s2[c], acc);
        out[b * 40 + t] = acc;
    }
}

// ---------------- host-side layer driver ----------------
static void run_layer(const float* Fext, int chanoff, int lda, int C, int O,
                      const float* W, const float* bias,
                      const float* bng, const float* bnb, int outoff) {
    // 1. squared norms
    sqnorm_kernel<<<(Bsz * Npt + 255) / 256, 256>>>(Fext, chanoff, lda, C);
    // 2. pairwise distances (per batch)
    gemm_kernel<true><<<dim3(Npt / 128, Npt / 64, Bsz), 256>>>(
        Fext, chanoff, lda, (long)Npt * lda, nullptr, 0, 0, Npt, (long)Npt * Npt, C);
    // 3. top-K
    topk_kernel<<<Bsz * Npt, 256>>>();
    // 4. folded weights
    weff_kernel<<<(2 * O * C + 255) / 256, 256>>>(W, O, C);
    // 5. feature GEMM: Y (B*N, 2O)
    gemm_kernel<false><<<dim3(Bsz * Npt / 128, (2 * O) / 64, 1), 256>>>(
        Fext, chanoff, lda, 0, nullptr, C, 1, 2 * O, 0, C);
    // 6. gather + bn + lrelu + max
    aggregate_kernel<<<Bsz * Npt, O>>>(O, bias, bng, bnb, outoff);
}

extern "C" void kernel_launch(void* const* d_in, const int* in_sizes, int n_in,
                              void* d_out, int out_size) {
    const float* x       = (const float*)d_in[0];
    const float* conv1_w = (const float*)d_in[1];
    const float* conv1_b = (const float*)d_in[2];
    const float* bn1_g   = (const float*)d_in[3];
    const float* bn1_b   = (const float*)d_in[4];
    const float* conv2_w = (const float*)d_in[5];
    const float* bn2_g   = (const float*)d_in[6];
    const float* bn2_b   = (const float*)d_in[7];
    const float* conv3_w = (const float*)d_in[8];
    const float* bn3_g   = (const float*)d_in[9];
    const float* bn3_b   = (const float*)d_in[10];
    const float* conv4_w = (const float*)d_in[11];
    const float* bn4_g   = (const float*)d_in[12];
    const float* bn4_b   = (const float*)d_in[13];
    const float* conv5_w = (const float*)d_in[14];
    const float* lin1_w  = (const float*)d_in[15];
    const float* bn6_g   = (const float*)d_in[16];
    const float* bn6_b   = (const float*)d_in[17];
    const float* lin2_w  = (const float*)d_in[18];
    const float* lin2_b  = (const float*)d_in[19];
    const float* bn7_g   = (const float*)d_in[20];
    const float* bn7_b   = (const float*)d_in[21];
    const float* lin3_w  = (const float*)d_in[22];
    const float* lin3_b  = (const float*)d_in[23];
    float* out = (float*)d_out;

    // Edge conv layers. Input points x are already point-major (B,N,3).
    run_layer(x,       0,   3,   3,   64, conv1_w, conv1_b, bn1_g, bn1_b, 0);
    run_layer(nullptr, 0,   512, 64,  64, conv2_w, nullptr, bn2_g, bn2_b, 64);
    run_layer(nullptr, 64,  512, 64,  128, conv3_w, nullptr, bn3_g, bn3_b, 128);
    run_layer(nullptr, 128, 512, 128, 256, conv4_w, nullptr, bn4_g, bn4_b, 256);

    // conv5: e[b,n,o] = conv5_w[o,:] . xc[b,n,:]   (output reuses g_dist)
    gemm_kernel<false><<<dim3(Bsz * Npt / 128, 1024 / 64, 1), 256>>>(
        nullptr, 0, 512, 0, conv5_w, 512, 0, 1024, 0, 512);

    // global max pool over N (chunked), then fused MLP head
    gpool_kernel<<<dim3(32, 4), 256>>>();
    mlp_kernel<<<Bsz, 256>>>(lin1_w, bn6_g, bn6_b, lin2_w, lin2_b,
                             bn7_g, bn7_b, lin3_w, lin3_b, out);
}

// round 2
// speedup vs baseline: 1.5288x; 1.5288x over previous
#include <cuda_runtime.h>
#include <cfloat>

#define Bsz 8
#define Npt 1024
#define KNN 20

// ---------------- scratch (device globals; no allocation) ----------------
__device__ float    g_xx[Bsz * Npt];                     // squared norms
__device__ float    g_dist[(size_t)Bsz * Npt * Npt];     // dist matrix
__device__ int      g_idx[Bsz * Npt * KNN];              // knn indices
__device__ float    g_xc[(size_t)Bsz * Npt * 512];       // concat features (B,N,512): x1|x2|x3|x4
__device__ float    g_Y[(size_t)Bsz * Npt * 512];        // per-layer GEMM output (B*N, 2*O)
__device__ float    g_Weff[92160];                       // folded weights, all layers
__device__ unsigned g_pool[Bsz * 1024];                  // global max pool (monotonic-uint encoded)

// Weff segment offsets (2O x C):  L1 128x3, L2 128x64, L3 256x64, L4 512x128
#define WOFF1 0
#define WOFF2 384
#define WOFF3 8576
#define WOFF4 24960
#define WEND  90496

// monotonic float<->uint encoding for atomicMax-based fp32 max
__device__ __forceinline__ unsigned fenc(float v) {
    unsigned u = __float_as_uint(v);
    return (u & 0x80000000u) ? ~u : (u | 0x80000000u);
}
__device__ __forceinline__ float fdec(unsigned u) {
    unsigned f = (u & 0x80000000u) ? (u ^ 0x80000000u) : ~u;
    return __uint_as_float(f);
}

// ---------------- prep: fold weights for all layers + init pool ----------------
__device__ __forceinline__ float weff_val(const float* __restrict__ W, int O, int C, int i) {
    int j = i / C, c = i - j * C;
    if (j < O) return W[(size_t)j * 2 * C + c];
    int jo = j - O;
    return W[(size_t)jo * 2 * C + C + c] - W[(size_t)jo * 2 * C + c];
}

__global__ void prep_kernel(const float* __restrict__ w1, const float* __restrict__ w2,
                            const float* __restrict__ w3, const float* __restrict__ w4) {
    int i = blockIdx.x * 256 + threadIdx.x;
    if (i < Bsz * 1024) g_pool[i] = 0u;
    if (i >= WEND) return;
    float v;
    if (i < WOFF2)      v = weff_val(w1, 64, 3, i - WOFF1);
    else if (i < WOFF3) v = weff_val(w2, 64, 64, i - WOFF2);
    else if (i < WOFF4) v = weff_val(w3, 128, 64, i - WOFF3);
    else                v = weff_val(w4, 256, 128, i - WOFF4);
    g_Weff[i] = v;
}

// ---------------- squared norms for layer-1 input (C=3) ----------------
__global__ void sqnorm1_kernel(const float* __restrict__ x) {
    int i = blockIdx.x * 256 + threadIdx.x;
    if (i >= Bsz * Npt) return;
    const float* p = x + (size_t)i * 3;
    g_xx[i] = p[0] * p[0] + p[1] * p[1] + p[2] * p[2];
}

// ---------------- 128x128x16 register-blocked GEMM ----------------
// C[r][c] = sum_k A[r][k] * Bt[c][k]   (both operands K-contiguous)
// DIST: Bt = A (SYRK, lower-triangle blocks only, mirrored), epi = 2*acc - xx[r] - xx[c]
// POOL: no store; per-column block max -> atomicMax into g_pool (conv5 fused pooling)
template <int KDIM, bool DIST, bool POOL>
__global__ void __launch_bounds__(256, 2)
gemm128_kernel(const float* __restrict__ Aext, int Aoff, int lda, long sA,
               const float* __restrict__ Bext, int Boff, int ldbb_in,
               int Csel, int ldc, long sC) {
    constexpr int NCHUNK = (KDIM + 15) / 16;
    __shared__ float As[16][132];
    __shared__ float Bs[16][132];

    const int tid = threadIdx.x;
    const int tx = tid & 15, ty = tid >> 4;
    const int z = blockIdx.z;

    int bx, by;
    if (DIST) {                       // decode lower-triangle block index
        int t = blockIdx.x;
        bx = 0;
        while (t >= bx + 1) { t -= bx + 1; bx++; }
        by = t;
    } else {
        bx = blockIdx.x; by = blockIdx.y;
    }
    const int row0 = bx * 128;
    const int col0 = by * 128;

    const float* Abase = Aext ? Aext : (g_xc + Aoff);
    const float* A = Abase + (size_t)z * sA;
    const float* Bt;
    int ldbb;
    if (DIST) { Bt = A; ldbb = lda; }
    else      { Bt = Bext ? Bext : (g_Weff + Boff); ldbb = ldbb_in; }

    float acc[8][8];
#pragma unroll
    for (int i = 0; i < 8; i++)
#pragma unroll
        for (int j = 0; j < 8; j++) acc[i][j] = 0.f;

    if (NCHUNK == 1) {
        // single chunk, predicated loads (covers KDIM=3)
#pragma unroll
        for (int l = 0; l < 8; l++) {
            int i = tid + l * 256;
            int r = i >> 4, k = i & 15;
            As[k][r] = (k < KDIM) ? A[(size_t)(row0 + r) * lda + k] : 0.f;
            int c = r;
            Bs[k][c] = (k < KDIM) ? Bt[(size_t)(col0 + c) * ldbb + k] : 0.f;
        }
        __syncthreads();
#pragma unroll
        for (int k = 0; k < 16; k++) {
            float4 a0 = *(const float4*)&As[k][ty * 4];
            float4 a1 = *(const float4*)&As[k][ty * 4 + 64];
            float4 b0 = *(const float4*)&Bs[k][tx * 4];
            float4 b1 = *(const float4*)&Bs[k][tx * 4 + 64];
            float av[8] = {a0.x, a0.y, a0.z, a0.w, a1.x, a1.y, a1.z, a1.w};
            float bv[8] = {b0.x, b0.y, b0.z, b0.w, b1.x, b1.y, b1.z, b1.w};
#pragma unroll
            for (int i = 0; i < 8; i++)
#pragma unroll
                for (int j = 0; j < 8; j++)
                    acc[i][j] = fmaf(av[i], bv[j], acc[i][j]);
        }
    } else {
        // multi-chunk, KDIM % 16 == 0, register-staged single-buffer pipeline
        float ra[8], rb[8];
#pragma unroll
        for (int l = 0; l < 8; l++) {                     // preload chunk 0
            int i = tid + l * 256;
            int r = i >> 4, k = i & 15;
            As[k][r] = A[(size_t)(row0 + r) * lda + k];
            Bs[k][r] = Bt[(size_t)(col0 + r) * ldbb + k];
        }
        __syncthreads();
        for (int ch = 0; ch < NCHUNK; ch++) {
            const int k0n = (ch + 1) * 16;
            if (ch + 1 < NCHUNK) {
#pragma unroll
                for (int l = 0; l < 8; l++) {
                    int i = tid + l * 256;
                    int r = i >> 4, k = i & 15;
                    ra[l] = A[(size_t)(row0 + r) * lda + k0n + k];
                    rb[l] = Bt[(size_t)(col0 + r) * ldbb + k0n + k];
                }
            }
#pragma unroll
            for (int k = 0; k < 16; k++) {
                float4 a0 = *(const float4*)&As[k][ty * 4];
                float4 a1 = *(const float4*)&As[k][ty * 4 + 64];
                float4 b0 = *(const float4*)&Bs[k][tx * 4];
                float4 b1 = *(const float4*)&Bs[k][tx * 4 + 64];
                float av[8] = {a0.x, a0.y, a0.z, a0.w, a1.x, a1.y, a1.z, a1.w};
                float bv[8] = {b0.x, b0.y, b0.z, b0.w, b1.x, b1.y, b1.z, b1.w};
#pragma unroll
                for (int i = 0; i < 8; i++)
#pragma unroll
                    for (int j = 0; j < 8; j++)
                        acc[i][j] = fmaf(av[i], bv[j], acc[i][j]);
            }
            if (ch + 1 < NCHUNK) {
                __syncthreads();
#pragma unroll
                for (int l = 0; l < 8; l++) {
                    int i = tid + l * 256;
                    int r = i >> 4, k = i & 15;
                    As[k][r] = ra[l];
                    Bs[k][r] = rb[l];
                }
                __syncthreads();
            }
        }
    }

    if (POOL) {
        // conv5 fused max-pool: reduce over the 128 rows of this tile, atomicMax per column
        __syncthreads();
#pragma unroll
        for (int j = 0; j < 8; j++) {
            float m = acc[0][j];
#pragma unroll
            for (int i = 1; i < 8; i++) m = fmaxf(m, acc[i][j]);
            int c = (j < 4) ? (tx * 4 + j) : (64 + tx * 4 + (j - 4));
            As[ty][c] = m;
        }
        __syncthreads();
        if (tid < 128) {
            float m = As[0][tid];
#pragma unroll
            for (int w = 1; w < 16; w++) m = fmaxf(m, As[w][tid]);
            int b = row0 >> 10;
            atomicMax(&g_pool[b * 1024 + col0 + tid], fenc(m));
        }
        return;
    }

    float* Cp = ((Csel == 0) ? g_dist : g_Y) + (size_t)z * sC;

    if (DIST) {
        const float* xx = g_xx + (size_t)z * Npt;
        float xr[8], xc8[8];
#pragma unroll
        for (int i = 0; i < 8; i++) {
            xr[i]  = xx[row0 + (i >> 2) * 64 + ty * 4 + (i & 3)];
            xc8[i] = xx[col0 + (i >> 2) * 64 + tx * 4 + (i & 3)];
        }
        // direct tile
#pragma unroll
        for (int i = 0; i < 8; i++) {
            int r = row0 + (i >> 2) * 64 + ty * 4 + (i & 3);
#pragma unroll
            for (int cs = 0; cs < 2; cs++) {
                float4 o;
                o.x = 2.f * acc[i][cs * 4 + 0] - xr[i] - xc8[cs * 4 + 0];
                o.y = 2.f * acc[i][cs * 4 + 1] - xr[i] - xc8[cs * 4 + 1];
                o.z = 2.f * acc[i][cs * 4 + 2] - xr[i] - xc8[cs * 4 + 2];
                o.w = 2.f * acc[i][cs * 4 + 3] - xr[i] - xc8[cs * 4 + 3];
                *(float4*)&Cp[(size_t)r * ldc + col0 + cs * 64 + tx * 4] = o;
            }
        }
        // mirrored tile (skip diagonal blocks)
        if (bx != by) {
#pragma unroll
            for (int j = 0; j < 8; j++) {
                int c = col0 + (j >> 2) * 64 + tx * 4 + (j & 3);
#pragma unroll
                for (int rs = 0; rs < 2; rs++) {
                    float4 o;
                    o.x = 2.f * acc[rs * 4 + 0][j] - xr[rs * 4 + 0] - xc8[j];
                    o.y = 2.f * acc[rs * 4 + 1][j] - xr[rs * 4 + 1] - xc8[j];
                    o.z = 2.f * acc[rs * 4 + 2][j] - xr[rs * 4 + 2] - xc8[j];
                    o.w = 2.f * acc[rs * 4 + 3][j] - xr[rs * 4 + 3] - xc8[j];
                    *(float4*)&Cp[(size_t)c * ldc + row0 + rs * 64 + ty * 4] = o;
                }
            }
        }
    } else {
#pragma unroll
        for (int i = 0; i < 8; i++) {
            int r = row0 + (i >> 2) * 64 + ty * 4 + (i & 3);
#pragma unroll
            for (int cs = 0; cs < 2; cs++) {
                float4 o;
                o.x = acc[i][cs * 4 + 0];
                o.y = acc[i][cs * 4 + 1];
                o.z = acc[i][cs * 4 + 2];
                o.w = acc[i][cs * 4 + 3];
                *(float4*)&Cp[(size_t)r * ldc + col0 + cs * 64 + tx * 4] = o;
            }
        }
    }
}

// ---------------- top-K (K=20): warp per row, lane-cached local max ----------------
__global__ void topk_kernel() {
    int row = (blockIdx.x << 3) + (threadIdx.x >> 5);
    int lane = threadIdx.x & 31;
    const float* rp = g_dist + (size_t)row * Npt + lane;
    float v[32];
#pragma unroll
    for (int j = 0; j < 32; j++) v[j] = rp[j * 32];
    float lm = v[0];
    int li = 0;
#pragma unroll
    for (int j = 1; j < 32; j++)
        if (v[j] > lm) { lm = v[j]; li = j; }   // strict > keeps lowest index per lane
    int gi = li * 32 + lane;
    for (int k = 0; k < KNN; k++) {
        float bv = lm;
        int bi = gi;
#pragma unroll
        for (int off = 16; off; off >>= 1) {
            float ov = __shfl_xor_sync(0xffffffffu, bv, off);
            int oi = __shfl_xor_sync(0xffffffffu, bi, off);
            if (ov > bv || (ov == bv && oi < bi)) { bv = ov; bi = oi; }
        }
        if (lane == 0) g_idx[row * KNN + k] = bi;
        if (gi == bi) {          // this lane owns the winner: remove & rescan
            int jr = bi >> 5;
#pragma unroll
            for (int j = 0; j < 32; j++)
                if (j == jr) v[j] = -FLT_MAX;
            lm = v[0]; li = 0;
#pragma unroll
            for (int j = 1; j < 32; j++)
                if (v[j] > lm) { lm = v[j]; li = j; }
            gi = li * 32 + lane;
        }
    }
}

// ---------------- gather + bias + bn + lrelu + max over K, fused next-layer sqnorm ----------------
__global__ void aggregate_kernel(int O, const float* __restrict__ bias,
                                 const float* __restrict__ bng, const float* __restrict__ bnb,
                                 int outoff) {
    int bn = blockIdx.x;
    int b = bn >> 10;
    int o = threadIdx.x;                               // blockDim == O
    __shared__ int sidx[KNN];
    __shared__ float sp[8];
    if (o < KNN) sidx[o] = g_idx[bn * KNN + o];
    __syncthreads();
    int twoO = 2 * O;
    const float* Yrow = g_Y + (size_t)bn * twoO;
    float ctr = Yrow[O + o];
    if (bias) ctr += bias[o];
    float scale = bng[o] * rsqrtf(1.0f + 1e-5f);
    float shift = bnb[o];
    const float* Yb = g_Y + (size_t)(b << 10) * twoO;
    float m = -FLT_MAX;
#pragma unroll
    for (int k = 0; k < KNN; k++) {
        float v = Yb[(size_t)sidx[k] * twoO + o] + ctr;
        v = fmaf(v, scale, shift);
        v = (v >= 0.f) ? v : 0.01f * v;
        m = fmaxf(m, v);
    }
    g_xc[(size_t)bn * 512 + outoff + o] = m;
    // fused squared-norm of this layer's output (next layer's xx)
    float s = m * m;
#pragma unroll
    for (int off = 16; off; off >>= 1) s += __shfl_xor_sync(0xffffffffu, s, off);
    if ((o & 31) == 0) sp[o >> 5] = s;
    __syncthreads();
    if (o == 0) {
        float t = 0.f;
        int nw = O >> 5;
        for (int w = 0; w < nw; w++) t += sp[w];
        g_xx[bn] = t;
    }
}

// ---------------- fused MLP head ----------------
__global__ void mlp_kernel(const float* __restrict__ lin1_w,
                           const float* __restrict__ bn6_g, const float* __restrict__ bn6_b,
                           const float* __restrict__ lin2_w, const float* __restrict__ lin2_b,
                           const float* __restrict__ bn7_g, const float* __restrict__ bn7_b,
                           const float* __restrict__ lin3_w, const float* __restrict__ lin3_b,
                           float* __restrict__ out) {
    int b = blockIdx.x, t = threadIdx.x;
    __shared__ float sy[1024];
    __shared__ float s1[512];
    __shared__ float s2[256];
    for (int i = t; i < 1024; i += 256) sy[i] = fdec(g_pool[b * 1024 + i]);
    __syncthreads();
    const float r = rsqrtf(1.0f + 1e-5f);
    for (int j = t; j < 512; j += 256) {
        const float* w = lin1_w + (size_t)j * 1024;
        float acc = 0.f;
        for (int c = 0; c < 1024; c++) acc = fmaf(w[c], sy[c], acc);
        float v = fmaf(acc, bn6_g[j] * r, bn6_b[j]);
        s1[j] = (v >= 0.f) ? v : 0.01f * v;
    }
    __syncthreads();
    {
        const float* w = lin2_w + (size_t)t * 512;
        float acc = lin2_b[t];
        for (int c = 0; c < 512; c++) acc = fmaf(w[c], s1[c], acc);
        float v = fmaf(acc, bn7_g[t] * r, bn7_b[t]);
        s2[t] = (v >= 0.f) ? v : 0.01f * v;
    }
    __syncthreads();
    if (t < 40) {
        const float* w = lin3_w + (size_t)t * 256;
        float acc = lin3_b[t];
        for (int c = 0; c < 256; c++) acc = fmaf(w[c], s2[c], acc);
        out[b * 40 + t] = acc;
    }
}

extern "C" void kernel_launch(void* const* d_in, const int* in_sizes, int n_in,
                              void* d_out, int out_size) {
    const float* x       = (const float*)d_in[0];
    const float* conv1_w = (const float*)d_in[1];
    const float* conv1_b = (const float*)d_in[2];
    const float* bn1_g   = (const float*)d_in[3];
    const float* bn1_b   = (const float*)d_in[4];
    const float* conv2_w = (const float*)d_in[5];
    const float* bn2_g   = (const float*)d_in[6];
    const float* bn2_b   = (const float*)d_in[7];
    const float* conv3_w = (const float*)d_in[8];
    const float* bn3_g   = (const float*)d_in[9];
    const float* bn3_b   = (const float*)d_in[10];
    const float* conv4_w = (const float*)d_in[11];
    const float* bn4_g   = (const float*)d_in[12];
    const float* bn4_b   = (const float*)d_in[13];
    const float* conv5_w = (const float*)d_in[14];
    const float* lin1_w  = (const float*)d_in[15];
    const float* bn6_g   = (const float*)d_in[16];
    const float* bn6_b   = (const float*)d_in[17];
    const float* lin2_w  = (const float*)d_in[18];
    const float* lin2_b  = (const float*)d_in[19];
    const float* bn7_g   = (const float*)d_in[20];
    const float* bn7_b   = (const float*)d_in[21];
    const float* lin3_w  = (const float*)d_in[22];
    const float* lin3_b  = (const float*)d_in[23];
    float* out = (float*)d_out;

    prep_kernel<<<(WEND + 255) / 256, 256>>>(conv1_w, conv2_w, conv3_w, conv4_w);
    sqnorm1_kernel<<<32, 256>>>(x);

    const long sDist = (long)Npt * Npt;
    // ----- layer 1 (C=3, O=64) -----
    gemm128_kernel<3, true, false><<<dim3(36, 1, Bsz), 256>>>(x, 0, 3, 3 * Npt, nullptr, 0, 0, 0, Npt, sDist);
    topk_kernel<<<Bsz * Npt / 8, 256>>>();
    gemm128_kernel<3, false, false><<<dim3(64, 1, 1), 256>>>(x, 0, 3, 0, nullptr, WOFF1, 3, 1, 128, 0);
    aggregate_kernel<<<Bsz * Npt, 64>>>(64, conv1_b, bn1_g, bn1_b, 0);
    // ----- layer 2 (C=64, O=64) -----
    gemm128_kernel<64, true, false><<<dim3(36, 1, Bsz), 256>>>(nullptr, 0, 512, 512 * Npt, nullptr, 0, 0, 0, Npt, sDist);
    topk_kernel<<<Bsz * Npt / 8, 256>>>();
    gemm128_kernel<64, false, false><<<dim3(64, 1, 1), 256>>>(nullptr, 0, 512, 0, nullptr, WOFF2, 64, 1, 128, 0);
    aggregate_kernel<<<Bsz * Npt, 64>>>(64, nullptr, bn2_g, bn2_b, 64);
    // ----- layer 3 (C=64, O=128) -----
    gemm128_kernel<64, true, false><<<dim3(36, 1, Bsz), 256>>>(nullptr, 64, 512, 512 * Npt, nullptr, 0, 0, 0, Npt, sDist);
    topk_kernel<<<Bsz * Npt / 8, 256>>>();
    gemm128_kernel<64, false, false><<<dim3(64, 2, 1), 256>>>(nullptr, 64, 512, 0, nullptr, WOFF3, 64, 1, 256, 0);
    aggregate_kernel<<<Bsz * Npt, 128>>>(128, nullptr, bn3_g, bn3_b, 128);
    // ----- layer 4 (C=128, O=256) -----
    gemm128_kernel<128, true, false><<<dim3(36, 1, Bsz), 256>>>(nullptr, 128, 512, 512 * Npt, nullptr, 0, 0, 0, Npt, sDist);
    topk_kernel<<<Bsz * Npt / 8, 256>>>();
    gemm128_kernel<128, false, false><<<dim3(64, 4, 1), 256>>>(nullptr, 128, 512, 0, nullptr, WOFF4, 128, 1, 512, 0);
    aggregate_kernel<<<Bsz * Npt, 256>>>(256, nullptr, bn4_g, bn4_b, 256);

    // ----- conv5 (K=512, N=1024) with fused global max-pool -----
    gemm128_kernel<512, false, true><<<dim3(64, 8, 1), 256>>>(nullptr, 0, 512, 0, conv5_w, 0, 512, 0, 0, 0);

    // ----- MLP head -----
    mlp_kernel<<<Bsz, 256>>>(lin1_w, bn6_g, bn6_b, lin2_w, lin2_b,
                             bn7_g, bn7_b, lin3_w, lin3_b, out);
}

// round 6
// speedup vs baseline: 1.7063x; 1.1161x over previous
#include <cuda_runtime.h>
#include <cuda_bf16.h>
#include <cfloat>
#include <cstdint>

#define Bsz 8
#define Npt 1024
#define KNN 20

// ---------------- scratch (device globals; no allocation) ----------------
__device__ float    g_xx[Bsz * Npt];                     // squared norms
__device__ float    g_dist[(size_t)Bsz * Npt * Npt];     // dist matrix; reused as conv5 C
__device__ int      g_idx[Bsz * Npt * KNN];              // knn indices
__device__ float    g_xc[(size_t)Bsz * Npt * 512];       // concat features (B,N,512): x1|x2|x3|x4
__device__ float    g_Y[(size_t)Bsz * Npt * 512];        // per-layer GEMM output (B*N, 2*O)
__device__ float    g_Weff[92160];                       // folded weights, all layers
__device__ unsigned g_pool[Bsz * 1024];                  // global max pool (monotonic-uint encoded)
__device__ __nv_bfloat16 g_Ah[(size_t)8192 * 512];       // conv5 A hi
__device__ __nv_bfloat16 g_Al[(size_t)8192 * 512];       // conv5 A lo
__device__ __nv_bfloat16 g_Bh[(size_t)1024 * 512];       // conv5 B hi
__device__ __nv_bfloat16 g_Bl[(size_t)1024 * 512];       // conv5 B lo

// Weff segment offsets (2O x C):  L1 128x3, L2 128x64, L3 256x64, L4 512x128
#define WOFF1 0
#define WOFF2 384
#define WOFF3 8576
#define WOFF4 24960
#define WEND  90496

// monotonic float<->uint encoding
__device__ __forceinline__ unsigned fenc(float v) {
    unsigned u = __float_as_uint(v);
    return (u & 0x80000000u) ? ~u : (u | 0x80000000u);
}
__device__ __forceinline__ float fdec(unsigned u) {
    unsigned f = (u & 0x80000000u) ? (u ^ 0x80000000u) : ~u;
    return __uint_as_float(f);
}

// bf16 mma.sync m16n8k16 (legacy tensor path — compiles for compute_103)
__device__ __forceinline__ void mma16816(float (&d)[4], const uint32_t (&a)[4],
                                         const uint32_t (&b)[2]) {
    asm volatile("mma.sync.aligned.m16n8k16.row.col.f32.bf16.bf16.f32 "
                 "{%0,%1,%2,%3}, {%4,%5,%6,%7}, {%8,%9}, {%0,%1,%2,%3};"
                 : "+f"(d[0]), "+f"(d[1]), "+f"(d[2]), "+f"(d[3])
                 : "r"(a[0]), "r"(a[1]), "r"(a[2]), "r"(a[3]), "r"(b[0]), "r"(b[1]));
}

// ---------------- prep: fold weights for all layers + init pool ----------------
__device__ __forceinline__ float weff_val(const float* __restrict__ W, int O, int C, int i) {
    int j = i / C, c = i - j * C;
    if (j < O) return W[(size_t)j * 2 * C + c];
    int jo = j - O;
    return W[(size_t)jo * 2 * C + C + c] - W[(size_t)jo * 2 * C + c];
}
__global__ void prep_kernel(const float* __restrict__ w1, const float* __restrict__ w2,
                            const float* __restrict__ w3, const float* __restrict__ w4) {
    int i = blockIdx.x * 256 + threadIdx.x;
    if (i < Bsz * 1024) g_pool[i] = 0u;
    if (i >= WEND) return;
    float v;
    if (i < WOFF2)      v = weff_val(w1, 64, 3, i - WOFF1);
    else if (i < WOFF3) v = weff_val(w2, 64, 64, i - WOFF2);
    else if (i < WOFF4) v = weff_val(w3, 128, 64, i - WOFF3);
    else                v = weff_val(w4, 256, 128, i - WOFF4);
    g_Weff[i] = v;
}

__global__ void sqnorm1_kernel(const float* __restrict__ x) {
    int i = blockIdx.x * 256 + threadIdx.x;
    if (i >= Bsz * Npt) return;
    const float* p = x + (size_t)i * 3;
    g_xx[i] = p[0] * p[0] + p[1] * p[1] + p[2] * p[2];
}

// ---------------- 128x128x16 register-blocked fp32 GEMM ----------------
template <int KDIM, bool DIST>
__global__ void __launch_bounds__(256, 2)
gemm128_kernel(const float* __restrict__ Aext, int Aoff, int lda, long sA,
               int Boff, int Csel, int ldc, long sC) {
    constexpr int NCHUNK = (KDIM + 15) / 16;
    __shared__ float As[16][132];
    __shared__ float Bs[16][132];

    const int tid = threadIdx.x;
    const int tx = tid & 15, ty = tid >> 4;
    const int z = blockIdx.z;

    int bx, by;
    if (DIST) {
        int t = blockIdx.x;
        bx = 0;
        while (t >= bx + 1) { t -= bx + 1; bx++; }
        by = t;
    } else {
        bx = blockIdx.x; by = blockIdx.y;
    }
    const int row0 = bx * 128;
    const int col0 = by * 128;

    const float* Abase = Aext ? Aext : (g_xc + Aoff);
    const float* A = Abase + (size_t)z * sA;
    const float* Bt;
    int ldbb;
    if (DIST) { Bt = A; ldbb = lda; }
    else      { Bt = g_Weff + Boff; ldbb = KDIM; }

    float acc[8][8];
#pragma unroll
    for (int i = 0; i < 8; i++)
#pragma unroll
        for (int j = 0; j < 8; j++) acc[i][j] = 0.f;

    if (NCHUNK == 1) {
#pragma unroll
        for (int l = 0; l < 8; l++) {
            int i = tid + l * 256;
            int r = i >> 4, k = i & 15;
            As[k][r] = (k < KDIM) ? A[(size_t)(row0 + r) * lda + k] : 0.f;
            Bs[k][r] = (k < KDIM) ? Bt[(size_t)(col0 + r) * ldbb + k] : 0.f;
        }
        __syncthreads();
#pragma unroll
        for (int k = 0; k < 16; k++) {
            float4 a0 = *(const float4*)&As[k][ty * 4];
            float4 a1 = *(const float4*)&As[k][ty * 4 + 64];
            float4 b0 = *(const float4*)&Bs[k][tx * 4];
            float4 b1 = *(const float4*)&Bs[k][tx * 4 + 64];
            float av[8] = {a0.x, a0.y, a0.z, a0.w, a1.x, a1.y, a1.z, a1.w};
            float bv[8] = {b0.x, b0.y, b0.z, b0.w, b1.x, b1.y, b1.z, b1.w};
#pragma unroll
            for (int i = 0; i < 8; i++)
#pragma unroll
                for (int j = 0; j < 8; j++)
                    acc[i][j] = fmaf(av[i], bv[j], acc[i][j]);
        }
    } else {
        float ra[8], rb[8];
#pragma unroll
        for (int l = 0; l < 8; l++) {
            int i = tid + l * 256;
            int r = i >> 4, k = i & 15;
            As[k][r] = A[(size_t)(row0 + r) * lda + k];
            Bs[k][r] = Bt[(size_t)(col0 + r) * ldbb + k];
        }
        __syncthreads();
        for (int ch = 0; ch < NCHUNK; ch++) {
            const int k0n = (ch + 1) * 16;
            if (ch + 1 < NCHUNK) {
#pragma unroll
                for (int l = 0; l < 8; l++) {
                    int i = tid + l * 256;
                    int r = i >> 4, k = i & 15;
                    ra[l] = A[(size_t)(row0 + r) * lda + k0n + k];
                    rb[l] = Bt[(size_t)(col0 + r) * ldbb + k0n + k];
                }
            }
#pragma unroll
            for (int k = 0; k < 16; k++) {
                float4 a0 = *(const float4*)&As[k][ty * 4];
                float4 a1 = *(const float4*)&As[k][ty * 4 + 64];
                float4 b0 = *(const float4*)&Bs[k][tx * 4];
                float4 b1 = *(const float4*)&Bs[k][tx * 4 + 64];
                float av[8] = {a0.x, a0.y, a0.z, a0.w, a1.x, a1.y, a1.z, a1.w};
                float bv[8] = {b0.x, b0.y, b0.z, b0.w, b1.x, b1.y, b1.z, b1.w};
#pragma unroll
                for (int i = 0; i < 8; i++)
#pragma unroll
                    for (int j = 0; j < 8; j++)
                        acc[i][j] = fmaf(av[i], bv[j], acc[i][j]);
            }
            if (ch + 1 < NCHUNK) {
                __syncthreads();
#pragma unroll
                for (int l = 0; l < 8; l++) {
                    int i = tid + l * 256;
                    int r = i >> 4, k = i & 15;
                    As[k][r] = ra[l];
                    Bs[k][r] = rb[l];
                }
                __syncthreads();
            }
        }
    }

    float* Cp = ((Csel == 0) ? g_dist : g_Y) + (size_t)z * sC;

    if (DIST) {
        const float* xx = g_xx + (size_t)z * Npt;
        float xr[8], xc8[8];
#pragma unroll
        for (int i = 0; i < 8; i++) {
            xr[i]  = xx[row0 + (i >> 2) * 64 + ty * 4 + (i & 3)];
            xc8[i] = xx[col0 + (i >> 2) * 64 + tx * 4 + (i & 3)];
        }
#pragma unroll
        for (int i = 0; i < 8; i++) {
            int r = row0 + (i >> 2) * 64 + ty * 4 + (i & 3);
#pragma unroll
            for (int cs = 0; cs < 2; cs++) {
                float4 o;
                o.x = 2.f * acc[i][cs * 4 + 0] - xr[i] - xc8[cs * 4 + 0];
                o.y = 2.f * acc[i][cs * 4 + 1] - xr[i] - xc8[cs * 4 + 1];
                o.z = 2.f * acc[i][cs * 4 + 2] - xr[i] - xc8[cs * 4 + 2];
                o.w = 2.f * acc[i][cs * 4 + 3] - xr[i] - xc8[cs * 4 + 3];
                *(float4*)&Cp[(size_t)r * ldc + col0 + cs * 64 + tx * 4] = o;
            }
        }
        if (bx != by) {
#pragma unroll
            for (int j = 0; j < 8; j++) {
                int c = col0 + (j >> 2) * 64 + tx * 4 + (j & 3);
#pragma unroll
                for (int rs = 0; rs < 2; rs++) {
                    float4 o;
                    o.x = 2.f * acc[rs * 4 + 0][j] - xr[rs * 4 + 0] - xc8[j];
                    o.y = 2.f * acc[rs * 4 + 1][j] - xr[rs * 4 + 1] - xc8[j];
                    o.z = 2.f * acc[rs * 4 + 2][j] - xr[rs * 4 + 2] - xc8[j];
                    o.w = 2.f * acc[rs * 4 + 3][j] - xr[rs * 4 + 3] - xc8[j];
                    *(float4*)&Cp[(size_t)c * ldc + row0 + rs * 64 + ty * 4] = o;
                }
            }
        }
    } else {
#pragma unroll
        for (int i = 0; i < 8; i++) {
            int r = row0 + (i >> 2) * 64 + ty * 4 + (i & 3);
#pragma unroll
            for (int cs = 0; cs < 2; cs++) {
                float4 o;
                o.x = acc[i][cs * 4 + 0];
                o.y = acc[i][cs * 4 + 1];
                o.z = acc[i][cs * 4 + 2];
                o.w = acc[i][cs * 4 + 3];
                *(float4*)&Cp[(size_t)r * ldc + col0 + cs * 64 + tx * 4] = o;
            }
        }
    }
}

// ---------------- top-K (K=20): warp per row, REDUX-based selection ----------------
__global__ void topk_kernel() {
    int row = (blockIdx.x << 3) + (threadIdx.x >> 5);
    int lane = threadIdx.x & 31;
    const float* rp = g_dist + (size_t)row * Npt + lane;
    float v[32];
#pragma unroll
    for (int j = 0; j < 32; j++) v[j] = rp[j * 32];
    float lm = v[0];
    int li = 0;
#pragma unroll
    for (int j = 1; j < 32; j++)
        if (v[j] > lm) { lm = v[j]; li = j; }       // strict > keeps lowest index per lane
    int gi = li * 32 + lane;
    for (int k = 0; k < KNN; k++) {
        unsigned mykey = fenc(lm);
        unsigned wmax = __reduce_max_sync(0xffffffffu, mykey);
        unsigned cand = (mykey == wmax) ? (unsigned)gi : 0xFFFFFFFFu;
        unsigned wini = __reduce_min_sync(0xffffffffu, cand);
        if (lane == 0) g_idx[row * KNN + k] = (int)wini;
        if (mykey == wmax && gi == (int)wini) {     // owner: remove & rescan
            int jr = gi >> 5;
#pragma unroll
            for (int j = 0; j < 32; j++)
                if (j == jr) v[j] = -FLT_MAX;
            lm = v[0]; li = 0;
#pragma unroll
            for (int j = 1; j < 32; j++)
                if (v[j] > lm) { lm = v[j]; li = j; }
            gi = li * 32 + lane;
        }
    }
}

// ---------------- gather + bias + bn + lrelu + max over K, fused next-layer sqnorm --------
__global__ void aggregate_kernel(int O, const float* __restrict__ bias,
                                 const float* __restrict__ bng, const float* __restrict__ bnb,
                                 int outoff) {
    int bn = blockIdx.x;
    int b = bn >> 10;
    int o = threadIdx.x;
    __shared__ int sidx[KNN];
    __shared__ float sp[8];
    if (o < KNN) sidx[o] = g_idx[bn * KNN + o];
    __syncthreads();
    int twoO = 2 * O;
    const float* Yrow = g_Y + (size_t)bn * twoO;
    float ctr = Yrow[O + o];
    if (bias) ctr += bias[o];
    float scale = bng[o] * rsqrtf(1.0f + 1e-5f);
    float shift = bnb[o];
    const float* Yb = g_Y + (size_t)(b << 10) * twoO;
    float m = -FLT_MAX;
#pragma unroll
    for (int k = 0; k < KNN; k++) {
        float v = Yb[(size_t)sidx[k] * twoO + o] + ctr;
        v = fmaf(v, scale, shift);
        v = (v >= 0.f) ? v : 0.01f * v;
        m = fmaxf(m, v);
    }
    g_xc[(size_t)bn * 512 + outoff + o] = m;
    float s = m * m;
#pragma unroll
    for (int off = 16; off; off >>= 1) s += __shfl_xor_sync(0xffffffffu, s, off);
    if ((o & 31) == 0) sp[o >> 5] = s;
    __syncthreads();
    if (o == 0) {
        float t = 0.f;
        int nw = O >> 5;
        for (int w = 0; w < nw; w++) t += sp[w];
        g_xx[bn] = t;
    }
}

// ---------------- bf16 hi/lo split conversions (write device globals DIRECTLY) --------
__global__ void cvtA_kernel() {
    int i = blockIdx.x * 256 + threadIdx.x;          // [0, 8192*512)
    float x = g_xc[i];
    __nv_bfloat16 h = __float2bfloat16(x);
    g_Ah[i] = h;
    g_Al[i] = __float2bfloat16(x - __bfloat162float(h));
}
__global__ void cvtB_kernel(const float* __restrict__ w5) {
    int i = blockIdx.x * 256 + threadIdx.x;          // [0, 1024*512)
    float x = w5[i];
    __nv_bfloat16 h = __float2bfloat16(x);
    g_Bh[i] = h;
    g_Bl[i] = __float2bfloat16(x - __bfloat162float(h));
}

// ---------------- conv5: bf16 mma.sync split GEMM, plain C store to g_dist ----------------
// C[8192,1024] = A[8192,512] * B[1024,512]^T; acc += Ah*Bh + Ah*Bl + Al*Bh (fp32 accum)
// CTA 128x128, 8 warps (4 along m, 2 along n), warp tile 32x64.
#define CKS 24   // bf16 row stride in smem (48B: conflict-free, 16B-aligned)

__global__ void __launch_bounds__(256, 1) conv5_mma_kernel() {
    __shared__ __nv_bfloat16 sAh[128 * CKS];
    __shared__ __nv_bfloat16 sAl[128 * CKS];
    __shared__ __nv_bfloat16 sBh[128 * CKS];
    __shared__ __nv_bfloat16 sBl[128 * CKS];

    const int tid = threadIdx.x;
    const int wid = tid >> 5, lane = tid & 31;
    const int warp_m = wid & 3, warp_n = wid >> 2;
    const int row0 = blockIdx.x * 128;
    const int col0 = blockIdx.y * 128;

    // global-load mapping: one uint4 (8 bf16) per thread per tile
    const int lr = tid >> 1;
    const int lkb = (tid & 1) * 8;
    const size_t aoff = (size_t)(row0 + lr) * 512 + lkb;
    const size_t boff = (size_t)(col0 + lr) * 512 + lkb;
    const int soff = lr * CKS + lkb;

    float acc[2][8][4];
#pragma unroll
    for (int mt = 0; mt < 2; mt++)
#pragma unroll
        for (int nt = 0; nt < 8; nt++)
#pragma unroll
            for (int f = 0; f < 4; f++) acc[mt][nt][f] = 0.f;

    // preload chunk 0
    {
        uint4 vah = *(const uint4*)&g_Ah[aoff];
        uint4 val_ = *(const uint4*)&g_Al[aoff];
        uint4 vbh = *(const uint4*)&g_Bh[boff];
        uint4 vbl = *(const uint4*)&g_Bl[boff];
        *(uint4*)&sAh[soff] = vah;
        *(uint4*)&sAl[soff] = val_;
        *(uint4*)&sBh[soff] = vbh;
        *(uint4*)&sBl[soff] = vbl;
    }
    __syncthreads();

    const int grp = lane >> 2;
    const int kq = (lane & 3) * 2;

    for (int ch = 0; ch < 32; ch++) {
        uint4 vah, val_, vbh, vbl;
        if (ch < 31) {
            int kk = (ch + 1) * 16;
            vah = *(const uint4*)&g_Ah[aoff + kk];
            val_ = *(const uint4*)&g_Al[aoff + kk];
            vbh = *(const uint4*)&g_Bh[boff + kk];
            vbl = *(const uint4*)&g_Bl[boff + kk];
        }
        // load fragments
        uint32_t ah[2][4], al[2][4], bh[8][2], bl[8][2];
#pragma unroll
        for (int mt = 0; mt < 2; mt++) {
            int r0 = (warp_m * 32 + mt * 16 + grp) * CKS;
            ah[mt][0] = *(const uint32_t*)&sAh[r0 + kq];
            ah[mt][1] = *(const uint32_t*)&sAh[r0 + 8 * CKS + kq];
            ah[mt][2] = *(const uint32_t*)&sAh[r0 + kq + 8];
            ah[mt][3] = *(const uint32_t*)&sAh[r0 + 8 * CKS + kq + 8];
            al[mt][0] = *(const uint32_t*)&sAl[r0 + kq];
            al[mt][1] = *(const uint32_t*)&sAl[r0 + 8 * CKS + kq];
            al[mt][2] = *(const uint32_t*)&sAl[r0 + kq + 8];
            al[mt][3] = *(const uint32_t*)&sAl[r0 + 8 * CKS + kq + 8];
        }
#pragma unroll
        for (int nt = 0; nt < 8; nt++) {
            int n0 = (warp_n * 64 + nt * 8 + grp) * CKS;
            bh[nt][0] = *(const uint32_t*)&sBh[n0 + kq];
            bh[nt][1] = *(const uint32_t*)&sBh[n0 + kq + 8];
            bl[nt][0] = *(const uint32_t*)&sBl[n0 + kq];
            bl[nt][1] = *(const uint32_t*)&sBl[n0 + kq + 8];
        }
#pragma unroll
        for (int mt = 0; mt < 2; mt++)
#pragma unroll
            for (int nt = 0; nt < 8; nt++) {
                mma16816(acc[mt][nt], ah[mt], bh[nt]);
                mma16816(acc[mt][nt], ah[mt], bl[nt]);
                mma16816(acc[mt][nt], al[mt], bh[nt]);
            }
        if (ch < 31) {
            __syncthreads();
            *(uint4*)&sAh[soff] = vah;
            *(uint4*)&sAl[soff] = val_;
            *(uint4*)&sBh[soff] = vbh;
            *(uint4*)&sBl[soff] = vbl;
            __syncthreads();
        }
    }

    // plain C store (canonical fragment layout -> g_dist[8192][1024])
    const int rbase = row0 + warp_m * 32;
    const int cbase = col0 + warp_n * 64;
#pragma unroll
    for (int mt = 0; mt < 2; mt++) {
        int r = rbase + mt * 16 + grp;
#pragma unroll
        for (int nt = 0; nt < 8; nt++) {
            int c = cbase + nt * 8 + kq;
            *(float2*)&g_dist[(size_t)r * 1024 + c] =
                make_float2(acc[mt][nt][0], acc[mt][nt][1]);
            *(float2*)&g_dist[(size_t)(r + 8) * 1024 + c] =
                make_float2(acc[mt][nt][2], acc[mt][nt][3]);
        }
    }
}

// ---------------- global max pool from conv5 C (g_dist) into g_pool ----------------
__global__ void gpool2_kernel() {
    // grid (32, 8): blockIdx.x = b*4 + ochunk; blockIdx.y = nchunk (128 points each)
    int b = blockIdx.x >> 2;
    int o = (blockIdx.x & 3) * 256 + threadIdx.x;
    const float* p = g_dist + ((size_t)(b * Npt) + blockIdx.y * 128) * 1024 + o;
    float m = -FLT_MAX;
#pragma unroll 4
    for (int n = 0; n < 128; n++) m = fmaxf(m, p[(size_t)n * 1024]);
    atomicMax(&g_pool[b * 1024 + o], fenc(m));
}

// ---------------- fused MLP head ----------------
__global__ void mlp_kernel(const float* __restrict__ lin1_w,
                           const float* __restrict__ bn6_g, const float* __restrict__ bn6_b,
                           const float* __restrict__ lin2_w, const float* __restrict__ lin2_b,
                           const float* __restrict__ bn7_g, const float* __restrict__ bn7_b,
                           const float* __restrict__ lin3_w, const float* __restrict__ lin3_b,
                           float* __restrict__ out) {
    int b = blockIdx.x, t = threadIdx.x;
    __shared__ float sy[1024];
    __shared__ float s1[512];
    __shared__ float s2[256];
    for (int i = t; i < 1024; i += 256) sy[i] = fdec(g_pool[b * 1024 + i]);
    __syncthreads();
    const float r = rsqrtf(1.0f + 1e-5f);
    for (int j = t; j < 512; j += 256) {
        const float* w = lin1_w + (size_t)j * 1024;
        float acc = 0.f;
        for (int c = 0; c < 1024; c++) acc = fmaf(w[c], sy[c], acc);
        float v = fmaf(acc, bn6_g[j] * r, bn6_b[j]);
        s1[j] = (v >= 0.f) ? v : 0.01f * v;
    }
    __syncthreads();
    {
        const float* w = lin2_w + (size_t)t * 512;
        float acc = lin2_b[t];
        for (int c = 0; c < 512; c++) acc = fmaf(w[c], s1[c], acc);
        float v = fmaf(acc, bn7_g[t] * r, bn7_b[t]);
        s2[t] = (v >= 0.f) ? v : 0.01f * v;
    }
    __syncthreads();
    if (t < 40) {
        const float* w = lin3_w + (size_t)t * 256;
        float acc = lin3_b[t];
        for (int c = 0; c < 256; c++) acc = fmaf(w[c], s2[c], acc);
        out[b * 40 + t] = acc;
    }
}

extern "C" void kernel_launch(void* const* d_in, const int* in_sizes, int n_in,
                              void* d_out, int out_size) {
    const float* x       = (const float*)d_in[0];
    const float* conv1_w = (const float*)d_in[1];
    const float* conv1_b = (const float*)d_in[2];
    const float* bn1_g   = (const float*)d_in[3];
    const float* bn1_b   = (const float*)d_in[4];
    const float* conv2_w = (const float*)d_in[5];
    const float* bn2_g   = (const float*)d_in[6];
    const float* bn2_b   = (const float*)d_in[7];
    const float* conv3_w = (const float*)d_in[8];
    const float* bn3_g   = (const float*)d_in[9];
    const float* bn3_b   = (const float*)d_in[10];
    const float* conv4_w = (const float*)d_in[11];
    const float* bn4_g   = (const float*)d_in[12];
    const float* bn4_b   = (const float*)d_in[13];
    const float* conv5_w = (const float*)d_in[14];
    const float* lin1_w  = (const float*)d_in[15];
    const float* bn6_g   = (const float*)d_in[16];
    const float* bn6_b   = (const float*)d_in[17];
    const float* lin2_w  = (const float*)d_in[18];
    const float* lin2_b  = (const float*)d_in[19];
    const float* bn7_g   = (const float*)d_in[20];
    const float* bn7_b   = (const float*)d_in[21];
    const float* lin3_w  = (const float*)d_in[22];
    const float* lin3_b  = (const float*)d_in[23];
    float* out = (float*)d_out;

    prep_kernel<<<(WEND + 255) / 256, 256>>>(conv1_w, conv2_w, conv3_w, conv4_w);
    sqnorm1_kernel<<<32, 256>>>(x);

    const long sDist = (long)Npt * Npt;
    // ----- layer 1 (C=3, O=64) -----
    gemm128_kernel<3, true><<<dim3(36, 1, Bsz), 256>>>(x, 0, 3, 3 * Npt, 0, 0, Npt, sDist);
    topk_kernel<<<Bsz * Npt / 8, 256>>>();
    gemm128_kernel<3, false><<<dim3(64, 1, 1), 256>>>(x, 0, 3, 0, WOFF1, 1, 128, 0);
    aggregate_kernel<<<Bsz * Npt, 64>>>(64, conv1_b, bn1_g, bn1_b, 0);
    // ----- layer 2 (C=64, O=64) -----
    gemm128_kernel<64, true><<<dim3(36, 1, Bsz), 256>>>(nullptr, 0, 512, 512 * Npt, 0, 0, Npt, sDist);
    topk_kernel<<<Bsz * Npt / 8, 256>>>();
    gemm128_kernel<64, false><<<dim3(64, 1, 1), 256>>>(nullptr, 0, 512, 0, WOFF2, 1, 128, 0);
    aggregate_kernel<<<Bsz * Npt, 64>>>(64, nullptr, bn2_g, bn2_b, 64);
    // ----- layer 3 (C=64, O=128) -----
    gemm128_kernel<64, true><<<dim3(36, 1, Bsz), 256>>>(nullptr, 64, 512, 512 * Npt, 0, 0, Npt, sDist);
    topk_kernel<<<Bsz * Npt / 8, 256>>>();
    gemm128_kernel<64, false><<<dim3(64, 2, 1), 256>>>(nullptr, 64, 512, 0, WOFF3, 1, 256, 0);
    aggregate_kernel<<<Bsz * Npt, 128>>>(128, nullptr, bn3_g, bn3_b, 128);
    // ----- layer 4 (C=128, O=256) -----
    gemm128_kernel<128, true><<<dim3(36, 1, Bsz), 256>>>(nullptr, 128, 512, 512 * Npt, 0, 0, Npt, sDist);
    topk_kernel<<<Bsz * Npt / 8, 256>>>();
    gemm128_kernel<128, false><<<dim3(64, 4, 1), 256>>>(nullptr, 128, 512, 0, WOFF4, 1, 512, 0);
    aggregate_kernel<<<Bsz * Npt, 256>>>(256, nullptr, bn4_g, bn4_b, 256);

    // ----- conv5: bf16-split mma.sync GEMM -> g_dist, then pool -----
    cvtA_kernel<<<8192 * 512 / 256, 256>>>();
    cvtB_kernel<<<1024 * 512 / 256, 256>>>(conv5_w);
    conv5_mma_kernel<<<dim3(64, 8), 256>>>();
    gpool2_kernel<<<dim3(32, 8), 256>>>();

    // ----- MLP head -----
    mlp_kernel<<<Bsz, 256>>>(lin1_w, bn6_g, bn6_b, lin2_w, lin2_b,
                             bn7_g, bn7_b, lin3_w, lin3_b, out);
}

// round 7
// speedup vs baseline: 2.0769x; 1.2172x over previous
#include <cuda_runtime.h>
#include <cuda_bf16.h>
#include <cfloat>
#include <cstdint>

#define Bsz 8
#define Npt 1024
#define KNN 20
#define CKS 24   // bf16 row stride in smem (48B: conflict-free, 16B-aligned)

// ---------------- scratch (device globals; no allocation) ----------------
__device__ float    g_xx[Bsz * Npt];                     // squared norms
__device__ float    g_dist[(size_t)Bsz * Npt * Npt];     // dist matrix
__device__ int      g_idx[Bsz * Npt * KNN];              // knn indices
__device__ float    g_Y[(size_t)Bsz * Npt * 512];        // per-layer GEMM output (B*N, 2*O)
__device__ float    g_Weff[92160];                       // folded weights fp32 (layer-1 use)
__device__ unsigned g_pool[Bsz * 1024];                  // global max pool (monotonic-uint)
__device__ __nv_bfloat16 g_Fh[(size_t)8192 * 512];       // features hi (x1|x2|x3|x4)
__device__ __nv_bfloat16 g_Fl[(size_t)8192 * 512];       // features lo
__device__ __nv_bfloat16 g_Wh[92160];                    // folded weights hi
__device__ __nv_bfloat16 g_Wl[92160];                    // folded weights lo
__device__ __nv_bfloat16 g_Bh[(size_t)1024 * 512];       // conv5 weight hi
__device__ __nv_bfloat16 g_Bl[(size_t)1024 * 512];       // conv5 weight lo

// Weff segment offsets (2O x C):  L1 128x3, L2 128x64, L3 256x64, L4 512x128
#define WOFF1 0
#define WOFF2 384
#define WOFF3 8576
#define WOFF4 24960
#define WEND  90496

// monotonic float<->uint encoding
__device__ __forceinline__ unsigned fenc(float v) {
    unsigned u = __float_as_uint(v);
    return (u & 0x80000000u) ? ~u : (u | 0x80000000u);
}
__device__ __forceinline__ float fdec(unsigned u) {
    unsigned f = (u & 0x80000000u) ? (u ^ 0x80000000u) : ~u;
    return __uint_as_float(f);
}

// bf16 mma.sync m16n8k16 (legacy tensor path — compiles for compute_103)
__device__ __forceinline__ void mma16816(float (&d)[4], const uint32_t (&a)[4],
                                         const uint32_t (&b)[2]) {
    asm volatile("mma.sync.aligned.m16n8k16.row.col.f32.bf16.bf16.f32 "
                 "{%0,%1,%2,%3}, {%4,%5,%6,%7}, {%8,%9}, {%0,%1,%2,%3};"
                 : "+f"(d[0]), "+f"(d[1]), "+f"(d[2]), "+f"(d[3])
                 : "r"(a[0]), "r"(a[1]), "r"(a[2]), "r"(a[3]), "r"(b[0]), "r"(b[1]));
}

// ---------------- prep: fold weights (fp32 + hi/lo bf16) + init pool ----------------
__device__ __forceinline__ float weff_val(const float* __restrict__ W, int O, int C, int i) {
    int j = i / C, c = i - j * C;
    if (j < O) return W[(size_t)j * 2 * C + c];
    int jo = j - O;
    return W[(size_t)jo * 2 * C + C + c] - W[(size_t)jo * 2 * C + c];
}
__global__ void prep_kernel(const float* __restrict__ w1, const float* __restrict__ w2,
                            const float* __restrict__ w3, const float* __restrict__ w4) {
    int i = blockIdx.x * 256 + threadIdx.x;
    if (i < Bsz * 1024) g_pool[i] = 0u;
    if (i >= WEND) return;
    float v;
    if (i < WOFF2)      v = weff_val(w1, 64, 3, i - WOFF1);
    else if (i < WOFF3) v = weff_val(w2, 64, 64, i - WOFF2);
    else if (i < WOFF4) v = weff_val(w3, 128, 64, i - WOFF3);
    else                v = weff_val(w4, 256, 128, i - WOFF4);
    g_Weff[i] = v;
    __nv_bfloat16 h = __float2bfloat16(v);
    g_Wh[i] = h;
    g_Wl[i] = __float2bfloat16(v - __bfloat162float(h));
}

__global__ void sqnorm1_kernel(const float* __restrict__ x) {
    int i = blockIdx.x * 256 + threadIdx.x;
    if (i >= Bsz * Npt) return;
    const float* p = x + (size_t)i * 3;
    g_xx[i] = p[0] * p[0] + p[1] * p[1] + p[2] * p[2];
}

// ---------------- layer-1 fp32 GEMM (K=3): DIST(SYRK) and FEAT ----------------
template <bool DIST>
__global__ void __launch_bounds__(256, 2)
gemm128_kernel(const float* __restrict__ Aext, int Boff, int Csel, int ldc, long sC) {
    constexpr int KDIM = 3;
    __shared__ float As[16][132];
    __shared__ float Bs[16][132];

    const int tid = threadIdx.x;
    const int tx = tid & 15, ty = tid >> 4;
    const int z = blockIdx.z;
    const int lda = 3;

    int bx, by;
    if (DIST) {
        int t = blockIdx.x;
        bx = 0;
        while (t >= bx + 1) { t -= bx + 1; bx++; }
        by = t;
    } else {
        bx = blockIdx.x; by = blockIdx.y;
    }
    const int row0 = bx * 128;
    const int col0 = by * 128;

    const float* A = Aext + (size_t)z * (DIST ? 3 * Npt : 0);
    const float* Bt;
    int ldbb;
    if (DIST) { Bt = A; ldbb = lda; }
    else      { Bt = g_Weff + Boff; ldbb = KDIM; }

    float acc[8][8];
#pragma unroll
    for (int i = 0; i < 8; i++)
#pragma unroll
        for (int j = 0; j < 8; j++) acc[i][j] = 0.f;

#pragma unroll
    for (int l = 0; l < 8; l++) {
        int i = tid + l * 256;
        int r = i >> 4, k = i & 15;
        As[k][r] = (k < KDIM) ? A[(size_t)(row0 + r) * lda + k] : 0.f;
        Bs[k][r] = (k < KDIM) ? Bt[(size_t)(col0 + r) * ldbb + k] : 0.f;
    }
    __syncthreads();
#pragma unroll
    for (int k = 0; k < 3; k++) {
        float4 a0 = *(const float4*)&As[k][ty * 4];
        float4 a1 = *(const float4*)&As[k][ty * 4 + 64];
        float4 b0 = *(const float4*)&Bs[k][tx * 4];
        float4 b1 = *(const float4*)&Bs[k][tx * 4 + 64];
        float av[8] = {a0.x, a0.y, a0.z, a0.w, a1.x, a1.y, a1.z, a1.w};
        float bv[8] = {b0.x, b0.y, b0.z, b0.w, b1.x, b1.y, b1.z, b1.w};
#pragma unroll
        for (int i = 0; i < 8; i++)
#pragma unroll
            for (int j = 0; j < 8; j++)
                acc[i][j] = fmaf(av[i], bv[j], acc[i][j]);
    }

    float* Cp = ((Csel == 0) ? g_dist : g_Y) + (size_t)z * sC;

    if (DIST) {
        const float* xx = g_xx + (size_t)z * Npt;
        float xr[8], xc8[8];
#pragma unroll
        for (int i = 0; i < 8; i++) {
            xr[i]  = xx[row0 + (i >> 2) * 64 + ty * 4 + (i & 3)];
            xc8[i] = xx[col0 + (i >> 2) * 64 + tx * 4 + (i & 3)];
        }
#pragma unroll
        for (int i = 0; i < 8; i++) {
            int r = row0 + (i >> 2) * 64 + ty * 4 + (i & 3);
#pragma unroll
            for (int cs = 0; cs < 2; cs++) {
                float4 o;
                o.x = 2.f * acc[i][cs * 4 + 0] - xr[i] - xc8[cs * 4 + 0];
                o.y = 2.f * acc[i][cs * 4 + 1] - xr[i] - xc8[cs * 4 + 1];
                o.z = 2.f * acc[i][cs * 4 + 2] - xr[i] - xc8[cs * 4 + 2];
                o.w = 2.f * acc[i][cs * 4 + 3] - xr[i] - xc8[cs * 4 + 3];
                *(float4*)&Cp[(size_t)r * ldc + col0 + cs * 64 + tx * 4] = o;
            }
        }
        if (bx != by) {
#pragma unroll
            for (int j = 0; j < 8; j++) {
                int c = col0 + (j >> 2) * 64 + tx * 4 + (j & 3);
#pragma unroll
                for (int rs = 0; rs < 2; rs++) {
                    float4 o;
                    o.x = 2.f * acc[rs * 4 + 0][j] - xr[rs * 4 + 0] - xc8[j];
                    o.y = 2.f * acc[rs * 4 + 1][j] - xr[rs * 4 + 1] - xc8[j];
                    o.z = 2.f * acc[rs * 4 + 2][j] - xr[rs * 4 + 2] - xc8[j];
                    o.w = 2.f * acc[rs * 4 + 3][j] - xr[rs * 4 + 3] - xc8[j];
                    *(float4*)&Cp[(size_t)c * ldc + row0 + rs * 64 + ty * 4] = o;
                }
            }
        }
    } else {
#pragma unroll
        for (int i = 0; i < 8; i++) {
            int r = row0 + (i >> 2) * 64 + ty * 4 + (i & 3);
#pragma unroll
            for (int cs = 0; cs < 2; cs++) {
                float4 o;
                o.x = acc[i][cs * 4 + 0];
                o.y = acc[i][cs * 4 + 1];
                o.z = acc[i][cs * 4 + 2];
                o.w = acc[i][cs * 4 + 3];
                *(float4*)&Cp[(size_t)r * ldc + col0 + cs * 64 + tx * 4] = o;
            }
        }
    }
}

// ---------------- unified bf16-split mma GEMM (layers 2-4) ----------------
// DIST: C[128,128] per (bx,by,z); A,B = features; epi dist -> g_dist
// FEAT: Y[8192, twoO] = F . Weff^T; plain store -> g_Y
template <int KCHUNKS, bool DIST>
__global__ void __launch_bounds__(256, 1)
mma_gemm_kernel(int chanoff, int woff, int twoO) {
    __shared__ __nv_bfloat16 sAh[128 * CKS];
    __shared__ __nv_bfloat16 sAl[128 * CKS];
    __shared__ __nv_bfloat16 sBh[128 * CKS];
    __shared__ __nv_bfloat16 sBl[128 * CKS];

    const int tid = threadIdx.x;
    const int wid = tid >> 5, lane = tid & 31;
    const int warp_m = wid & 3, warp_n = wid >> 2;
    const int lr = tid >> 1, lkb = (tid & 1) * 8;
    const int grp = lane >> 2, kq = (lane & 3) * 2;
    const int soff = lr * CKS + lkb;

    size_t aoff, boff;
    const __nv_bfloat16 *Bh_, *Bl_;
    if (DIST) {
        aoff = (size_t)(blockIdx.z * 1024 + blockIdx.x * 128 + lr) * 512 + chanoff + lkb;
        boff = (size_t)(blockIdx.z * 1024 + blockIdx.y * 128 + lr) * 512 + chanoff + lkb;
        Bh_ = g_Fh; Bl_ = g_Fl;
    } else {
        aoff = (size_t)(blockIdx.x * 128 + lr) * 512 + chanoff + lkb;
        boff = (size_t)(blockIdx.y * 128 + lr) * (KCHUNKS * 16) + lkb;
        Bh_ = g_Wh + woff; Bl_ = g_Wl + woff;
    }

    float acc[2][8][4];
#pragma unroll
    for (int mt = 0; mt < 2; mt++)
#pragma unroll
        for (int nt = 0; nt < 8; nt++)
#pragma unroll
            for (int f = 0; f < 4; f++) acc[mt][nt][f] = 0.f;

    // preload chunk 0
    {
        uint4 vah = *(const uint4*)&g_Fh[aoff];
        uint4 val_ = *(const uint4*)&g_Fl[aoff];
        uint4 vbh = *(const uint4*)&Bh_[boff];
        uint4 vbl = *(const uint4*)&Bl_[boff];
        *(uint4*)&sAh[soff] = vah;
        *(uint4*)&sAl[soff] = val_;
        *(uint4*)&sBh[soff] = vbh;
        *(uint4*)&sBl[soff] = vbl;
    }
    __syncthreads();

#pragma unroll
    for (int ch = 0; ch < KCHUNKS; ch++) {
        uint4 vah, val_, vbh, vbl;
        if (ch + 1 < KCHUNKS) {
            int kk = (ch + 1) * 16;
            vah = *(const uint4*)&g_Fh[aoff + kk];
            val_ = *(const uint4*)&g_Fl[aoff + kk];
            vbh = *(const uint4*)&Bh_[boff + kk];
            vbl = *(const uint4*)&Bl_[boff + kk];
        }
        uint32_t ah[2][4], al[2][4], bh[8][2], bl[8][2];
#pragma unroll
        for (int mt = 0; mt < 2; mt++) {
            int r0 = (warp_m * 32 + mt * 16 + grp) * CKS;
            ah[mt][0] = *(const uint32_t*)&sAh[r0 + kq];
            ah[mt][1] = *(const uint32_t*)&sAh[r0 + 8 * CKS + kq];
            ah[mt][2] = *(const uint32_t*)&sAh[r0 + kq + 8];
            ah[mt][3] = *(const uint32_t*)&sAh[r0 + 8 * CKS + kq + 8];
            al[mt][0] = *(const uint32_t*)&sAl[r0 + kq];
            al[mt][1] = *(const uint32_t*)&sAl[r0 + 8 * CKS + kq];
            al[mt][2] = *(const uint32_t*)&sAl[r0 + kq + 8];
            al[mt][3] = *(const uint32_t*)&sAl[r0 + 8 * CKS + kq + 8];
        }
#pragma unroll
        for (int nt = 0; nt < 8; nt++) {
            int n0 = (warp_n * 64 + nt * 8 + grp) * CKS;
            bh[nt][0] = *(const uint32_t*)&sBh[n0 + kq];
            bh[nt][1] = *(const uint32_t*)&sBh[n0 + kq + 8];
            bl[nt][0] = *(const uint32_t*)&sBl[n0 + kq];
            bl[nt][1] = *(const uint32_t*)&sBl[n0 + kq + 8];
        }
#pragma unroll
        for (int mt = 0; mt < 2; mt++)
#pragma unroll
            for (int nt = 0; nt < 8; nt++) {
                mma16816(acc[mt][nt], ah[mt], bh[nt]);
                mma16816(acc[mt][nt], ah[mt], bl[nt]);
                mma16816(acc[mt][nt], al[mt], bh[nt]);
            }
        if (ch + 1 < KCHUNKS) {
            __syncthreads();
            *(uint4*)&sAh[soff] = vah;
            *(uint4*)&sAl[soff] = val_;
            *(uint4*)&sBh[soff] = vbh;
            *(uint4*)&sBl[soff] = vbl;
            __syncthreads();
        }
    }

    if (DIST) {
        const float* xx = g_xx + (size_t)blockIdx.z * Npt;
        float* Cp = g_dist + (size_t)blockIdx.z * Npt * Npt;
        const int rb = blockIdx.x * 128 + warp_m * 32;
        const int cb = blockIdx.y * 128 + warp_n * 64;
        float xr[2][2];
#pragma unroll
        for (int mt = 0; mt < 2; mt++) {
            xr[mt][0] = xx[rb + mt * 16 + grp];
            xr[mt][1] = xx[rb + mt * 16 + grp + 8];
        }
#pragma unroll
        for (int nt = 0; nt < 8; nt++) {
            int c = cb + nt * 8 + kq;
            float xc0 = xx[c], xc1 = xx[c + 1];
#pragma unroll
            for (int mt = 0; mt < 2; mt++) {
                int r = rb + mt * 16 + grp;
                *(float2*)&Cp[(size_t)r * Npt + c] = make_float2(
                    2.f * acc[mt][nt][0] - xr[mt][0] - xc0,
                    2.f * acc[mt][nt][1] - xr[mt][0] - xc1);
                *(float2*)&Cp[(size_t)(r + 8) * Npt + c] = make_float2(
                    2.f * acc[mt][nt][2] - xr[mt][1] - xc0,
                    2.f * acc[mt][nt][3] - xr[mt][1] - xc1);
            }
        }
    } else {
        const int rb = blockIdx.x * 128 + warp_m * 32;
        const int cb = blockIdx.y * 128 + warp_n * 64;
#pragma unroll
        for (int mt = 0; mt < 2; mt++) {
            int r = rb + mt * 16 + grp;
#pragma unroll
            for (int nt = 0; nt < 8; nt++) {
                int c = cb + nt * 8 + kq;
                *(float2*)&g_Y[(size_t)r * twoO + c] =
                    make_float2(acc[mt][nt][0], acc[mt][nt][1]);
                *(float2*)&g_Y[(size_t)(r + 8) * twoO + c] =
                    make_float2(acc[mt][nt][2], acc[mt][nt][3]);
            }
        }
    }
}

// ---------------- top-K (K=20): warp/row, REDUX select + 2-level rescan ----------------
__global__ void topk_kernel() {
    int row = (blockIdx.x << 3) + (threadIdx.x >> 5);
    int lane = threadIdx.x & 31;
    const float* rp = g_dist + (size_t)row * Npt + lane;
    float v[32];
#pragma unroll
    for (int j = 0; j < 32; j++) v[j] = rp[j * 32];
    // per-lane group maxes (4 groups of 8); strict > keeps lowest j per group
    float gm[4];
    int gj[4];
#pragma unroll
    for (int g = 0; g < 4; g++) {
        gm[g] = v[g * 8]; gj[g] = g * 8;
#pragma unroll
        for (int j = 1; j < 8; j++)
            if (v[g * 8 + j] > gm[g]) { gm[g] = v[g * 8 + j]; gj[g] = g * 8 + j; }
    }
    float lm = gm[0];
    int li = gj[0];
#pragma unroll
    for (int g = 1; g < 4; g++)
        if (gm[g] > lm) { lm = gm[g]; li = gj[g]; }
    int gi = li * 32 + lane;

    for (int k = 0; k < KNN; k++) {
        unsigned mykey = fenc(lm);
        unsigned wmax = __reduce_max_sync(0xffffffffu, mykey);
        unsigned cand = (mykey == wmax) ? (unsigned)gi : 0xFFFFFFFFu;
        unsigned wini = __reduce_min_sync(0xffffffffu, cand);
        if (lane == 0) g_idx[row * KNN + k] = (int)wini;
        if (mykey == wmax && gi == (int)wini) {   // owner: clear + rescan its group only
            int jr = li, gr = li >> 3;
#pragma unroll
            for (int g = 0; g < 4; g++)
                if (g == gr) {
#pragma unroll
                    for (int j = 0; j < 8; j++)
                        if (g * 8 + j == jr) v[g * 8 + j] = -FLT_MAX;
                    gm[g] = v[g * 8]; gj[g] = g * 8;
#pragma unroll
                    for (int j = 1; j < 8; j++)
                        if (v[g * 8 + j] > gm[g]) { gm[g] = v[g * 8 + j]; gj[g] = g * 8 + j; }
                }
            lm = gm[0]; li = gj[0];
#pragma unroll
            for (int g = 1; g < 4; g++)
                if (gm[g] > lm) { lm = gm[g]; li = gj[g]; }
            gi = li * 32 + lane;
        }
    }
}

// ---- gather + bias + bn + lrelu + max over K; emit bf16 hi/lo features + sqnorm ----
__global__ void aggregate_kernel(int O, const float* __restrict__ bias,
                                 const float* __restrict__ bng, const float* __restrict__ bnb,
                                 int outoff) {
    int bn = blockIdx.x;
    int b = bn >> 10;
    int o = threadIdx.x;
    __shared__ int sidx[KNN];
    __shared__ float sp[8];
    if (o < KNN) sidx[o] = g_idx[bn * KNN + o];
    __syncthreads();
    int twoO = 2 * O;
    const float* Yrow = g_Y + (size_t)bn * twoO;
    float ctr = Yrow[O + o];
    if (bias) ctr += bias[o];
    float scale = bng[o] * rsqrtf(1.0f + 1e-5f);
    float shift = bnb[o];
    const float* Yb = g_Y + (size_t)(b << 10) * twoO;
    float m = -FLT_MAX;
#pragma unroll
    for (int k = 0; k < KNN; k++) {
        float v = Yb[(size_t)sidx[k] * twoO + o] + ctr;
        v = fmaf(v, scale, shift);
        v = (v >= 0.f) ? v : 0.01f * v;
        m = fmaxf(m, v);
    }
    __nv_bfloat16 h = __float2bfloat16(m);
    g_Fh[(size_t)bn * 512 + outoff + o] = h;
    g_Fl[(size_t)bn * 512 + outoff + o] = __float2bfloat16(m - __bfloat162float(h));
    float s = m * m;
#pragma unroll
    for (int off = 16; off; off >>= 1) s += __shfl_xor_sync(0xffffffffu, s, off);
    if ((o & 31) == 0) sp[o >> 5] = s;
    __syncthreads();
    if (o == 0) {
        float t = 0.f;
        int nw = O >> 5;
        for (int w = 0; w < nw; w++) t += sp[w];
        g_xx[bn] = t;
    }
}

// ---------------- conv5 weight split ----------------
__global__ void cvtB_kernel(const float* __restrict__ w5) {
    int i = blockIdx.x * 256 + threadIdx.x;          // [0, 1024*512)
    float x = w5[i];
    __nv_bfloat16 h = __float2bfloat16(x);
    g_Bh[i] = h;
    g_Bl[i] = __float2bfloat16(x - __bfloat162float(h));
}

// ------- conv5: bf16-split mma GEMM (K=512) with fused global max-pool -------
__global__ void __launch_bounds__(256, 1) conv5_mma_kernel() {
    __shared__ __nv_bfloat16 sAh[128 * CKS];
    __shared__ __nv_bfloat16 sAl[128 * CKS];
    __shared__ __nv_bfloat16 sBh[128 * CKS];
    __shared__ __nv_bfloat16 sBl[128 * CKS];

    const int tid = threadIdx.x;
    const int wid = tid >> 5, lane = tid & 31;
    const int warp_m = wid & 3, warp_n = wid >> 2;
    const int row0 = blockIdx.x * 128;
    const int col0 = blockIdx.y * 128;
    const int batch = row0 >> 10;

    const int lr = tid >> 1;
    const int lkb = (tid & 1) * 8;
    const size_t aoff = (size_t)(row0 + lr) * 512 + lkb;
    const size_t boff = (size_t)(col0 + lr) * 512 + lkb;
    const int soff = lr * CKS + lkb;

    float acc[2][8][4];
#pragma unroll
    for (int mt = 0; mt < 2; mt++)
#pragma unroll
        for (int nt = 0; nt < 8; nt++)
#pragma unroll
            for (int f = 0; f < 4; f++) acc[mt][nt][f] = 0.f;

    {
        uint4 vah = *(const uint4*)&g_Fh[aoff];
        uint4 val_ = *(const uint4*)&g_Fl[aoff];
        uint4 vbh = *(const uint4*)&g_Bh[boff];
        uint4 vbl = *(const uint4*)&g_Bl[boff];
        *(uint4*)&sAh[soff] = vah;
        *(uint4*)&sAl[soff] = val_;
        *(uint4*)&sBh[soff] = vbh;
        *(uint4*)&sBl[soff] = vbl;
    }
    __syncthreads();

    const int grp = lane >> 2;
    const int kq = (lane & 3) * 2;

    for (int ch = 0; ch < 32; ch++) {
        uint4 vah, val_, vbh, vbl;
        if (ch < 31) {
            int kk = (ch + 1) * 16;
            vah = *(const uint4*)&g_Fh[aoff + kk];
            val_ = *(const uint4*)&g_Fl[aoff + kk];
            vbh = *(const uint4*)&g_Bh[boff + kk];
            vbl = *(const uint4*)&g_Bl[boff + kk];
        }
        uint32_t ah[2][4], al[2][4], bh[8][2], bl[8][2];
#pragma unroll
        for (int mt = 0; mt < 2; mt++) {
            int r0 = (warp_m * 32 + mt * 16 + grp) * CKS;
            ah[mt][0] = *(const uint32_t*)&sAh[r0 + kq];
            ah[mt][1] = *(const uint32_t*)&sAh[r0 + 8 * CKS + kq];
            ah[mt][2] = *(const uint32_t*)&sAh[r0 + kq + 8];
            ah[mt][3] = *(const uint32_t*)&sAh[r0 + 8 * CKS + kq + 8];
            al[mt][0] = *(const uint32_t*)&sAl[r0 + kq];
            al[mt][1] = *(const uint32_t*)&sAl[r0 + 8 * CKS + kq];
            al[mt][2] = *(const uint32_t*)&sAl[r0 + kq + 8];
            al[mt][3] = *(const uint32_t*)&sAl[r0 + 8 * CKS + kq + 8];
        }
#pragma unroll
        for (int nt = 0; nt < 8; nt++) {
            int n0 = (warp_n * 64 + nt * 8 + grp) * CKS;
            bh[nt][0] = *(const uint32_t*)&sBh[n0 + kq];
            bh[nt][1] = *(const uint32_t*)&sBh[n0 + kq + 8];
            bl[nt][0] = *(const uint32_t*)&sBl[n0 + kq];
            bl[nt][1] = *(const uint32_t*)&sBl[n0 + kq + 8];
        }
#pragma unroll
        for (int mt = 0; mt < 2; mt++)
#pragma unroll
            for (int nt = 0; nt < 8; nt++) {
                mma16816(acc[mt][nt], ah[mt], bh[nt]);
                mma16816(acc[mt][nt], ah[mt], bl[nt]);
                mma16816(acc[mt][nt], al[mt], bh[nt]);
            }
        if (ch < 31) {
            __syncthreads();
            *(uint4*)&sAh[soff] = vah;
            *(uint4*)&sAl[soff] = val_;
            *(uint4*)&sBh[soff] = vbh;
            *(uint4*)&sBl[soff] = vbl;
            __syncthreads();
        }
    }

    // fused max-pool epilogue: max over this CTA's 128 rows, atomicMax per column
    float cmax[8][2];
#pragma unroll
    for (int nt = 0; nt < 8; nt++) {
        cmax[nt][0] = fmaxf(fmaxf(acc[0][nt][0], acc[0][nt][2]),
                            fmaxf(acc[1][nt][0], acc[1][nt][2]));
        cmax[nt][1] = fmaxf(fmaxf(acc[0][nt][1], acc[0][nt][3]),
                            fmaxf(acc[1][nt][1], acc[1][nt][3]));
    }
#pragma unroll
    for (int off = 16; off >= 4; off >>= 1)
#pragma unroll
        for (int nt = 0; nt < 8; nt++) {
            cmax[nt][0] = fmaxf(cmax[nt][0], __shfl_xor_sync(0xffffffffu, cmax[nt][0], off));
            cmax[nt][1] = fmaxf(cmax[nt][1], __shfl_xor_sync(0xffffffffu, cmax[nt][1], off));
        }
    if (lane < 4) {
        unsigned* pp = &g_pool[batch * 1024 + col0 + warp_n * 64];
#pragma unroll
        for (int nt = 0; nt < 8; nt++) {
            atomicMax(&pp[nt * 8 + lane * 2], fenc(cmax[nt][0]));
            atomicMax(&pp[nt * 8 + lane * 2 + 1], fenc(cmax[nt][1]));
        }
    }
}

// ---------------- fused MLP head ----------------
__global__ void mlp_kernel(const float* __restrict__ lin1_w,
                           const float* __restrict__ bn6_g, const float* __restrict__ bn6_b,
                           const float* __restrict__ lin2_w, const float* __restrict__ lin2_b,
                           const float* __restrict__ bn7_g, const float* __restrict__ bn7_b,
                           const float* __restrict__ lin3_w, const float* __restrict__ lin3_b,
                           float* __restrict__ out) {
    int b = blockIdx.x, t = threadIdx.x;
    __shared__ float sy[1024];
    __shared__ float s1[512];
    __shared__ float s2[256];
    for (int i = t; i < 1024; i += 256) sy[i] = fdec(g_pool[b * 1024 + i]);
    __syncthreads();
    const float r = rsqrtf(1.0f + 1e-5f);
    for (int j = t; j < 512; j += 256) {
        const float* w = lin1_w + (size_t)j * 1024;
        float acc = 0.f;
        for (int c = 0; c < 1024; c++) acc = fmaf(w[c], sy[c], acc);
        float v = fmaf(acc, bn6_g[j] * r, bn6_b[j]);
        s1[j] = (v >= 0.f) ? v : 0.01f * v;
    }
    __syncthreads();
    {
        const float* w = lin2_w + (size_t)t * 512;
        float acc = lin2_b[t];
        for (int c = 0; c < 512; c++) acc = fmaf(w[c], s1[c], acc);
        float v = fmaf(acc, bn7_g[t] * r, bn7_b[t]);
        s2[t] = (v >= 0.f) ? v : 0.01f * v;
    }
    __syncthreads();
    if (t < 40) {
        const float* w = lin3_w + (size_t)t * 256;
        float acc = lin3_b[t];
        for (int c = 0; c < 256; c++) acc = fmaf(w[c], s2[c], acc);
        out[b * 40 + t] = acc;
    }
}

extern "C" void kernel_launch(void* const* d_in, const int* in_sizes, int n_in,
                              void* d_out, int out_size) {
    const float* x       = (const float*)d_in[0];
    const float* conv1_w = (const float*)d_in[1];
    const float* conv1_b = (const float*)d_in[2];
    const float* bn1_g   = (const float*)d_in[3];
    const float* bn1_b   = (const float*)d_in[4];
    const float* conv2_w = (const float*)d_in[5];
    const float* bn2_g   = (const float*)d_in[6];
    const float* bn2_b   = (const float*)d_in[7];
    const float* conv3_w = (const float*)d_in[8];
    const float* bn3_g   = (const float*)d_in[9];
    const float* bn3_b   = (const float*)d_in[10];
    const float* conv4_w = (const float*)d_in[11];
    const float* bn4_g   = (const float*)d_in[12];
    const float* bn4_b   = (const float*)d_in[13];
    const float* conv5_w = (const float*)d_in[14];
    const float* lin1_w  = (const float*)d_in[15];
    const float* bn6_g   = (const float*)d_in[16];
    const float* bn6_b   = (const float*)d_in[17];
    const float* lin2_w  = (const float*)d_in[18];
    const float* lin2_b  = (const float*)d_in[19];
    const float* bn7_g   = (const float*)d_in[20];
    const float* bn7_b   = (const float*)d_in[21];
    const float* lin3_w  = (const float*)d_in[22];
    const float* lin3_b  = (const float*)d_in[23];
    float* out = (float*)d_out;

    prep_kernel<<<(WEND + 255) / 256, 256>>>(conv1_w, conv2_w, conv3_w, conv4_w);
    cvtB_kernel<<<1024 * 512 / 256, 256>>>(conv5_w);
    sqnorm1_kernel<<<32, 256>>>(x);

    const long sDist = (long)Npt * Npt;
    // ----- layer 1 (C=3, O=64): fp32 path -----
    gemm128_kernel<true><<<dim3(36, 1, Bsz), 256>>>(x, 0, 0, Npt, sDist);
    topk_kernel<<<Bsz * Npt / 8, 256>>>();
    gemm128_kernel<false><<<dim3(64, 1, 1), 256>>>(x, WOFF1, 1, 128, 0);
    aggregate_kernel<<<Bsz * Npt, 64>>>(64, conv1_b, bn1_g, bn1_b, 0);
    // ----- layer 2 (C=64, O=64): bf16 mma -----
    mma_gemm_kernel<4, true><<<dim3(8, 8, Bsz), 256>>>(0, 0, 0);
    topk_kernel<<<Bsz * Npt / 8, 256>>>();
    mma_gemm_kernel<4, false><<<dim3(64, 1), 256>>>(0, WOFF2, 128);
    aggregate_kernel<<<Bsz * Npt, 64>>>(64, nullptr, bn2_g, bn2_b, 64);
    // ----- layer 3 (C=64, O=128) -----
    mma_gemm_kernel<4, true><<<dim3(8, 8, Bsz), 256>>>(64, 0, 0);
    topk_kernel<<<Bsz * Npt / 8, 256>>>();
    mma_gemm_kernel<4, false><<<dim3(64, 2), 256>>>(64, WOFF3, 256);
    aggregate_kernel<<<Bsz * Npt, 128>>>(128, nullptr, bn3_g, bn3_b, 128);
    // ----- layer 4 (C=128, O=256) -----
    mma_gemm_kernel<8, true><<<dim3(8, 8, Bsz), 256>>>(128, 0, 0);
    topk_kernel<<<Bsz * Npt / 8, 256>>>();
    mma_gemm_kernel<8, false><<<dim3(64, 4), 256>>>(128, WOFF4, 512);
    aggregate_kernel<<<Bsz * Npt, 256>>>(256, nullptr, bn4_g, bn4_b, 256);

    // ----- conv5 (K=512) with fused global max-pool -----
    conv5_mma_kernel<<<dim3(64, 8), 256>>>();

    // ----- MLP head -----
    mlp_kernel<<<Bsz, 256>>>(lin1_w, bn6_g, bn6_b, lin2_w, lin2_b,
                             bn7_g, bn7_b, lin3_w, lin3_b, out);
}

// round 8
// speedup vs baseline: 2.1801x; 1.0497x over previous
#include <cuda_runtime.h>
#include <cuda_bf16.h>
#include <cfloat>
#include <cstdint>

#define Bsz 8
#define Npt 1024
#define KNN 20
#define CKS 24   // bf16 row stride in smem (48B: conflict-free, 16B-aligned)
#define BUFB (128 * CKS * 2)   // bytes per smem buffer (6144)

// ---------------- scratch (device globals; no allocation) ----------------
__device__ float    g_xx[Bsz * Npt];                     // squared norms
__device__ float    g_dist[(size_t)Bsz * Npt * Npt];     // dist matrix
__device__ int      g_idx[Bsz * Npt * KNN];              // knn indices
__device__ float    g_Y[(size_t)Bsz * Npt * 512];        // per-layer GEMM output (B*N, 2*O)
__device__ float    g_Weff[92160];                       // folded weights fp32 (layer-1 use)
__device__ unsigned g_pool[Bsz * 1024];                  // global max pool (monotonic-uint)
__device__ __nv_bfloat16 g_Fh[(size_t)8192 * 512];       // features hi (x1|x2|x3|x4)
__device__ __nv_bfloat16 g_Fl[(size_t)8192 * 512];       // features lo
__device__ __nv_bfloat16 g_Wh[92160];                    // folded weights hi
__device__ __nv_bfloat16 g_Wl[92160];                    // folded weights lo
__device__ __nv_bfloat16 g_Bh[(size_t)1024 * 512];       // conv5 weight hi
__device__ __nv_bfloat16 g_Bl[(size_t)1024 * 512];       // conv5 weight lo

// Weff segment offsets (2O x C):  L1 128x3, L2 128x64, L3 256x64, L4 512x128
#define WOFF1 0
#define WOFF2 384
#define WOFF3 8576
#define WOFF4 24960
#define WEND  90496

// monotonic float<->uint encoding
__device__ __forceinline__ unsigned fenc(float v) {
    unsigned u = __float_as_uint(v);
    return (u & 0x80000000u) ? ~u : (u | 0x80000000u);
}
__device__ __forceinline__ float fdec(unsigned u) {
    unsigned f = (u & 0x80000000u) ? (u ^ 0x80000000u) : ~u;
    return __uint_as_float(f);
}

// bf16 mma.sync m16n8k16 (legacy tensor path — compiles for compute_103)
__device__ __forceinline__ void mma16816(float (&d)[4], const uint32_t (&a)[4],
                                         const uint32_t (&b)[2]) {
    asm volatile("mma.sync.aligned.m16n8k16.row.col.f32.bf16.bf16.f32 "
                 "{%0,%1,%2,%3}, {%4,%5,%6,%7}, {%8,%9}, {%0,%1,%2,%3};"
                 : "+f"(d[0]), "+f"(d[1]), "+f"(d[2]), "+f"(d[3])
                 : "r"(a[0]), "r"(a[1]), "r"(a[2]), "r"(a[3]), "r"(b[0]), "r"(b[1]));
}

// cp.async helpers (sm_80+ PTX — legal on compute_103)
__device__ __forceinline__ void cpa16(uint32_t saddr, const void* g) {
    asm volatile("cp.async.cg.shared.global [%0], [%1], 16;" :: "r"(saddr), "l"(g));
}
#define CPA_COMMIT() asm volatile("cp.async.commit_group;")
#define CPA_WAIT0()  asm volatile("cp.async.wait_group 0;")

// ---------------- prep: fold weights (fp32 + hi/lo bf16) + init pool ----------------
__device__ __forceinline__ float weff_val(const float* __restrict__ W, int O, int C, int i) {
    int j = i / C, c = i - j * C;
    if (j < O) return W[(size_t)j * 2 * C + c];
    int jo = j - O;
    return W[(size_t)jo * 2 * C + C + c] - W[(size_t)jo * 2 * C + c];
}
__global__ void prep_kernel(const float* __restrict__ w1, const float* __restrict__ w2,
                            const float* __restrict__ w3, const float* __restrict__ w4) {
    int i = blockIdx.x * 256 + threadIdx.x;
    if (i < Bsz * 1024) g_pool[i] = 0u;
    if (i >= WEND) return;
    float v;
    if (i < WOFF2)      v = weff_val(w1, 64, 3, i - WOFF1);
    else if (i < WOFF3) v = weff_val(w2, 64, 64, i - WOFF2);
    else if (i < WOFF4) v = weff_val(w3, 128, 64, i - WOFF3);
    else                v = weff_val(w4, 256, 128, i - WOFF4);
    g_Weff[i] = v;
    __nv_bfloat16 h = __float2bfloat16(v);
    g_Wh[i] = h;
    g_Wl[i] = __float2bfloat16(v - __bfloat162float(h));
}

__global__ void sqnorm1_kernel(const float* __restrict__ x) {
    int i = blockIdx.x * 256 + threadIdx.x;
    if (i >= Bsz * Npt) return;
    const float* p = x + (size_t)i * 3;
    g_xx[i] = p[0] * p[0] + p[1] * p[1] + p[2] * p[2];
}

// ---------------- layer-1 fp32 GEMM (K=3): DIST(SYRK) and FEAT ----------------
template <bool DIST>
__global__ void __launch_bounds__(256, 2)
gemm128_kernel(const float* __restrict__ Aext, int Boff, int Csel, int ldc, long sC) {
    constexpr int KDIM = 3;
    __shared__ float As[16][132];
    __shared__ float Bs[16][132];

    const int tid = threadIdx.x;
    const int tx = tid & 15, ty = tid >> 4;
    const int z = blockIdx.z;
    const int lda = 3;

    int bx, by;
    if (DIST) {
        int t = blockIdx.x;
        bx = 0;
        while (t >= bx + 1) { t -= bx + 1; bx++; }
        by = t;
    } else {
        bx = blockIdx.x; by = blockIdx.y;
    }
    const int row0 = bx * 128;
    const int col0 = by * 128;

    const float* A = Aext + (size_t)z * (DIST ? 3 * Npt : 0);
    const float* Bt;
    int ldbb;
    if (DIST) { Bt = A; ldbb = lda; }
    else      { Bt = g_Weff + Boff; ldbb = KDIM; }

    float acc[8][8];
#pragma unroll
    for (int i = 0; i < 8; i++)
#pragma unroll
        for (int j = 0; j < 8; j++) acc[i][j] = 0.f;

#pragma unroll
    for (int l = 0; l < 8; l++) {
        int i = tid + l * 256;
        int r = i >> 4, k = i & 15;
        As[k][r] = (k < KDIM) ? A[(size_t)(row0 + r) * lda + k] : 0.f;
        Bs[k][r] = (k < KDIM) ? Bt[(size_t)(col0 + r) * ldbb + k] : 0.f;
    }
    __syncthreads();
#pragma unroll
    for (int k = 0; k < 3; k++) {
        float4 a0 = *(const float4*)&As[k][ty * 4];
        float4 a1 = *(const float4*)&As[k][ty * 4 + 64];
        float4 b0 = *(const float4*)&Bs[k][tx * 4];
        float4 b1 = *(const float4*)&Bs[k][tx * 4 + 64];
        float av[8] = {a0.x, a0.y, a0.z, a0.w, a1.x, a1.y, a1.z, a1.w};
        float bv[8] = {b0.x, b0.y, b0.z, b0.w, b1.x, b1.y, b1.z, b1.w};
#pragma unroll
        for (int i = 0; i < 8; i++)
#pragma unroll
            for (int j = 0; j < 8; j++)
                acc[i][j] = fmaf(av[i], bv[j], acc[i][j]);
    }

    float* Cp = ((Csel == 0) ? g_dist : g_Y) + (size_t)z * sC;

    if (DIST) {
        const float* xx = g_xx + (size_t)z * Npt;
        float xr[8], xc8[8];
#pragma unroll
        for (int i = 0; i < 8; i++) {
            xr[i]  = xx[row0 + (i >> 2) * 64 + ty * 4 + (i & 3)];
            xc8[i] = xx[col0 + (i >> 2) * 64 + tx * 4 + (i & 3)];
        }
#pragma unroll
        for (int i = 0; i < 8; i++) {
            int r = row0 + (i >> 2) * 64 + ty * 4 + (i & 3);
#pragma unroll
            for (int cs = 0; cs < 2; cs++) {
                float4 o;
                o.x = 2.f * acc[i][cs * 4 + 0] - xr[i] - xc8[cs * 4 + 0];
                o.y = 2.f * acc[i][cs * 4 + 1] - xr[i] - xc8[cs * 4 + 1];
                o.z = 2.f * acc[i][cs * 4 + 2] - xr[i] - xc8[cs * 4 + 2];
                o.w = 2.f * acc[i][cs * 4 + 3] - xr[i] - xc8[cs * 4 + 3];
                *(float4*)&Cp[(size_t)r * ldc + col0 + cs * 64 + tx * 4] = o;
            }
        }
        if (bx != by) {
#pragma unroll
            for (int j = 0; j < 8; j++) {
                int c = col0 + (j >> 2) * 64 + tx * 4 + (j & 3);
#pragma unroll
                for (int rs = 0; rs < 2; rs++) {
                    float4 o;
                    o.x = 2.f * acc[rs * 4 + 0][j] - xr[rs * 4 + 0] - xc8[j];
                    o.y = 2.f * acc[rs * 4 + 1][j] - xr[rs * 4 + 1] - xc8[j];
                    o.z = 2.f * acc[rs * 4 + 2][j] - xr[rs * 4 + 2] - xc8[j];
                    o.w = 2.f * acc[rs * 4 + 3][j] - xr[rs * 4 + 3] - xc8[j];
                    *(float4*)&Cp[(size_t)c * ldc + row0 + rs * 64 + ty * 4] = o;
                }
            }
        }
    } else {
#pragma unroll
        for (int i = 0; i < 8; i++) {
            int r = row0 + (i >> 2) * 64 + ty * 4 + (i & 3);
#pragma unroll
            for (int cs = 0; cs < 2; cs++) {
                float4 o;
                o.x = acc[i][cs * 4 + 0];
                o.y = acc[i][cs * 4 + 1];
                o.z = acc[i][cs * 4 + 2];
                o.w = acc[i][cs * 4 + 3];
                *(float4*)&Cp[(size_t)r * ldc + col0 + cs * 64 + tx * 4] = o;
            }
        }
    }
}

// ---------------- unified bf16-split mma GEMM (layers 2-4) ----------------
// cp.async double-buffered, occupancy 2, one __syncthreads per K-chunk.
template <int KCHUNKS, bool DIST>
__global__ void __launch_bounds__(256, 2)
mma_gemm_kernel(int chanoff, int woff, int twoO) {
    __shared__ __nv_bfloat16 sAh[2][128 * CKS];
    __shared__ __nv_bfloat16 sAl[2][128 * CKS];
    __shared__ __nv_bfloat16 sBh[2][128 * CKS];
    __shared__ __nv_bfloat16 sBl[2][128 * CKS];

    const int tid = threadIdx.x;
    const int wid = tid >> 5, lane = tid & 31;
    const int warp_m = wid & 3, warp_n = wid >> 2;
    const int lr = tid >> 1, lkb = (tid & 1) * 8;
    const int grp = lane >> 2, kq = (lane & 3) * 2;
    const int soffB = (lr * CKS + lkb) * 2;   // bytes

    size_t aoff, boff;
    const __nv_bfloat16 *Bh_, *Bl_;
    if (DIST) {
        aoff = (size_t)(blockIdx.z * 1024 + blockIdx.x * 128 + lr) * 512 + chanoff + lkb;
        boff = (size_t)(blockIdx.z * 1024 + blockIdx.y * 128 + lr) * 512 + chanoff + lkb;
        Bh_ = g_Fh; Bl_ = g_Fl;
    } else {
        aoff = (size_t)(blockIdx.x * 128 + lr) * 512 + chanoff + lkb;
        boff = (size_t)(blockIdx.y * 128 + lr) * (KCHUNKS * 16) + lkb;
        Bh_ = g_Wh + woff; Bl_ = g_Wl + woff;
    }

    const uint32_t sah = (uint32_t)__cvta_generic_to_shared(sAh[0]) + soffB;
    const uint32_t sal = (uint32_t)__cvta_generic_to_shared(sAl[0]) + soffB;
    const uint32_t sbh = (uint32_t)__cvta_generic_to_shared(sBh[0]) + soffB;
    const uint32_t sbl = (uint32_t)__cvta_generic_to_shared(sBl[0]) + soffB;

    float acc[2][8][4];
#pragma unroll
    for (int mt = 0; mt < 2; mt++)
#pragma unroll
        for (int nt = 0; nt < 8; nt++)
#pragma unroll
            for (int f = 0; f < 4; f++) acc[mt][nt][f] = 0.f;

    // issue chunk 0 into buf 0
    cpa16(sah, &g_Fh[aoff]);
    cpa16(sal, &g_Fl[aoff]);
    cpa16(sbh, &Bh_[boff]);
    cpa16(sbl, &Bl_[boff]);
    CPA_COMMIT();
    CPA_WAIT0();
    __syncthreads();

#pragma unroll
    for (int ch = 0; ch < KCHUNKS; ch++) {
        const int buf = ch & 1;
        if (ch + 1 < KCHUNKS) {
            const int nb = (ch + 1) & 1;
            const int kk = (ch + 1) * 16;
            cpa16(sah + nb * BUFB, &g_Fh[aoff + kk]);
            cpa16(sal + nb * BUFB, &g_Fl[aoff + kk]);
            cpa16(sbh + nb * BUFB, &Bh_[boff + kk]);
            cpa16(sbl + nb * BUFB, &Bl_[boff + kk]);
            CPA_COMMIT();
        }
        uint32_t ah[2][4], al[2][4], bh[8][2], bl[8][2];
#pragma unroll
        for (int mt = 0; mt < 2; mt++) {
            int r0 = (warp_m * 32 + mt * 16 + grp) * CKS;
            ah[mt][0] = *(const uint32_t*)&sAh[buf][r0 + kq];
            ah[mt][1] = *(const uint32_t*)&sAh[buf][r0 + 8 * CKS + kq];
            ah[mt][2] = *(const uint32_t*)&sAh[buf][r0 + kq + 8];
            ah[mt][3] = *(const uint32_t*)&sAh[buf][r0 + 8 * CKS + kq + 8];
            al[mt][0] = *(const uint32_t*)&sAl[buf][r0 + kq];
            al[mt][1] = *(const uint32_t*)&sAl[buf][r0 + 8 * CKS + kq];
            al[mt][2] = *(const uint32_t*)&sAl[buf][r0 + kq + 8];
            al[mt][3] = *(const uint32_t*)&sAl[buf][r0 + 8 * CKS + kq + 8];
        }
#pragma unroll
        for (int nt = 0; nt < 8; nt++) {
            int n0 = (warp_n * 64 + nt * 8 + grp) * CKS;
            bh[nt][0] = *(const uint32_t*)&sBh[buf][n0 + kq];
            bh[nt][1] = *(const uint32_t*)&sBh[buf][n0 + kq + 8];
            bl[nt][0] = *(const uint32_t*)&sBl[buf][n0 + kq];
            bl[nt][1] = *(const uint32_t*)&sBl[buf][n0 + kq + 8];
        }
#pragma unroll
        for (int mt = 0; mt < 2; mt++)
#pragma unroll
            for (int nt = 0; nt < 8; nt++) {
                mma16816(acc[mt][nt], ah[mt], bh[nt]);
                mma16816(acc[mt][nt], ah[mt], bl[nt]);
                mma16816(acc[mt][nt], al[mt], bh[nt]);
            }
        if (ch + 1 < KCHUNKS) {
            CPA_WAIT0();
            __syncthreads();
        }
    }

    if (DIST) {
        const float* xx = g_xx + (size_t)blockIdx.z * Npt;
        float* Cp = g_dist + (size_t)blockIdx.z * Npt * Npt;
        const int rb = blockIdx.x * 128 + warp_m * 32;
        const int cb = blockIdx.y * 128 + warp_n * 64;
        float xr[2][2];
#pragma unroll
        for (int mt = 0; mt < 2; mt++) {
            xr[mt][0] = xx[rb + mt * 16 + grp];
            xr[mt][1] = xx[rb + mt * 16 + grp + 8];
        }
#pragma unroll
        for (int nt = 0; nt < 8; nt++) {
            int c = cb + nt * 8 + kq;
            float xc0 = xx[c], xc1 = xx[c + 1];
#pragma unroll
            for (int mt = 0; mt < 2; mt++) {
                int r = rb + mt * 16 + grp;
                *(float2*)&Cp[(size_t)r * Npt + c] = make_float2(
                    2.f * acc[mt][nt][0] - xr[mt][0] - xc0,
                    2.f * acc[mt][nt][1] - xr[mt][0] - xc1);
                *(float2*)&Cp[(size_t)(r + 8) * Npt + c] = make_float2(
                    2.f * acc[mt][nt][2] - xr[mt][1] - xc0,
                    2.f * acc[mt][nt][3] - xr[mt][1] - xc1);
            }
        }
    } else {
        const int rb = blockIdx.x * 128 + warp_m * 32;
        const int cb = blockIdx.y * 128 + warp_n * 64;
#pragma unroll
        for (int mt = 0; mt < 2; mt++) {
            int r = rb + mt * 16 + grp;
#pragma unroll
            for (int nt = 0; nt < 8; nt++) {
                int c = cb + nt * 8 + kq;
                *(float2*)&g_Y[(size_t)r * twoO + c] =
                    make_float2(acc[mt][nt][0], acc[mt][nt][1]);
                *(float2*)&g_Y[(size_t)(r + 8) * twoO + c] =
                    make_float2(acc[mt][nt][2], acc[mt][nt][3]);
            }
        }
    }
}

// ---------------- top-K (K=20): warp/row, REDUX select + 2-level rescan ----------------
__global__ void topk_kernel() {
    int row = (blockIdx.x << 3) + (threadIdx.x >> 5);
    int lane = threadIdx.x & 31;
    const float* rp = g_dist + (size_t)row * Npt + lane;
    float v[32];
#pragma unroll
    for (int j = 0; j < 32; j++) v[j] = rp[j * 32];
    float gm[4];
    int gj[4];
#pragma unroll
    for (int g = 0; g < 4; g++) {
        gm[g] = v[g * 8]; gj[g] = g * 8;
#pragma unroll
        for (int j = 1; j < 8; j++)
            if (v[g * 8 + j] > gm[g]) { gm[g] = v[g * 8 + j]; gj[g] = g * 8 + j; }
    }
    float lm = gm[0];
    int li = gj[0];
#pragma unroll
    for (int g = 1; g < 4; g++)
        if (gm[g] > lm) { lm = gm[g]; li = gj[g]; }
    int gi = li * 32 + lane;

    for (int k = 0; k < KNN; k++) {
        unsigned mykey = fenc(lm);
        unsigned wmax = __reduce_max_sync(0xffffffffu, mykey);
        unsigned cand = (mykey == wmax) ? (unsigned)gi : 0xFFFFFFFFu;
        unsigned wini = __reduce_min_sync(0xffffffffu, cand);
        if (lane == 0) g_idx[row * KNN + k] = (int)wini;
        if (mykey == wmax && gi == (int)wini) {
            int jr = li, gr = li >> 3;
#pragma unroll
            for (int g = 0; g < 4; g++)
                if (g == gr) {
#pragma unroll
                    for (int j = 0; j < 8; j++)
                        if (g * 8 + j == jr) v[g * 8 + j] = -FLT_MAX;
                    gm[g] = v[g * 8]; gj[g] = g * 8;
#pragma unroll
                    for (int j = 1; j < 8; j++)
                        if (v[g * 8 + j] > gm[g]) { gm[g] = v[g * 8 + j]; gj[g] = g * 8 + j; }
                }
            lm = gm[0]; li = gj[0];
#pragma unroll
            for (int g = 1; g < 4; g++)
                if (gm[g] > lm) { lm = gm[g]; li = gj[g]; }
            gi = li * 32 + lane;
        }
    }
}

// ---- gather + bias + bn + lrelu + max over K; emit bf16 hi/lo features + sqnorm ----
__global__ void aggregate_kernel(int O, const float* __restrict__ bias,
                                 const float* __restrict__ bng, const float* __restrict__ bnb,
                                 int outoff) {
    int bn = blockIdx.x;
    int b = bn >> 10;
    int o = threadIdx.x;
    __shared__ int sidx[KNN];
    __shared__ float sp[8];
    if (o < KNN) sidx[o] = g_idx[bn * KNN + o];
    __syncthreads();
    int twoO = 2 * O;
    const float* Yrow = g_Y + (size_t)bn * twoO;
    float ctr = Yrow[O + o];
    if (bias) ctr += bias[o];
    float scale = bng[o] * rsqrtf(1.0f + 1e-5f);
    float shift = bnb[o];
    const float* Yb = g_Y + (size_t)(b << 10) * twoO;
    float m = -FLT_MAX;
#pragma unroll
    for (int k = 0; k < KNN; k++) {
        float v = Yb[(size_t)sidx[k] * twoO + o] + ctr;
        v = fmaf(v, scale, shift);
        v = (v >= 0.f) ? v : 0.01f * v;
        m = fmaxf(m, v);
    }
    __nv_bfloat16 h = __float2bfloat16(m);
    g_Fh[(size_t)bn * 512 + outoff + o] = h;
    g_Fl[(size_t)bn * 512 + outoff + o] = __float2bfloat16(m - __bfloat162float(h));
    float s = m * m;
#pragma unroll
    for (int off = 16; off; off >>= 1) s += __shfl_xor_sync(0xffffffffu, s, off);
    if ((o & 31) == 0) sp[o >> 5] = s;
    __syncthreads();
    if (o == 0) {
        float t = 0.f;
        int nw = O >> 5;
        for (int w = 0; w < nw; w++) t += sp[w];
        g_xx[bn] = t;
    }
}

// ---------------- conv5 weight split ----------------
__global__ void cvtB_kernel(const float* __restrict__ w5) {
    int i = blockIdx.x * 256 + threadIdx.x;          // [0, 1024*512)
    float x = w5[i];
    __nv_bfloat16 h = __float2bfloat16(x);
    g_Bh[i] = h;
    g_Bl[i] = __float2bfloat16(x - __bfloat162float(h));
}

// ------- conv5: bf16-split mma GEMM (K=512), cp.async pipeline, fused max-pool -------
__global__ void __launch_bounds__(256, 2) conv5_mma_kernel() {
    __shared__ __nv_bfloat16 sAh[2][128 * CKS];
    __shared__ __nv_bfloat16 sAl[2][128 * CKS];
    __shared__ __nv_bfloat16 sBh[2][128 * CKS];
    __shared__ __nv_bfloat16 sBl[2][128 * CKS];

    const int tid = threadIdx.x;
    const int wid = tid >> 5, lane = tid & 31;
    const int warp_m = wid & 3, warp_n = wid >> 2;
    const int row0 = blockIdx.x * 128;
    const int col0 = blockIdx.y * 128;
    const int batch = row0 >> 10;

    const int lr = tid >> 1;
    const int lkb = (tid & 1) * 8;
    const size_t aoff = (size_t)(row0 + lr) * 512 + lkb;
    const size_t boff = (size_t)(col0 + lr) * 512 + lkb;
    const int soffB = (lr * CKS + lkb) * 2;

    const uint32_t sah = (uint32_t)__cvta_generic_to_shared(sAh[0]) + soffB;
    const uint32_t sal = (uint32_t)__cvta_generic_to_shared(sAl[0]) + soffB;
    const uint32_t sbh = (uint32_t)__cvta_generic_to_shared(sBh[0]) + soffB;
    const uint32_t sbl = (uint32_t)__cvta_generic_to_shared(sBl[0]) + soffB;

    float acc[2][8][4];
#pragma unroll
    for (int mt = 0; mt < 2; mt++)
#pragma unroll
        for (int nt = 0; nt < 8; nt++)
#pragma unroll
            for (int f = 0; f < 4; f++) acc[mt][nt][f] = 0.f;

    cpa16(sah, &g_Fh[aoff]);
    cpa16(sal, &g_Fl[aoff]);
    cpa16(sbh, &g_Bh[boff]);
    cpa16(sbl, &g_Bl[boff]);
    CPA_COMMIT();
    CPA_WAIT0();
    __syncthreads();

    const int grp = lane >> 2;
    const int kq = (lane & 3) * 2;

    for (int ch = 0; ch < 32; ch++) {
        const int buf = ch & 1;
        if (ch < 31) {
            const int nb = (ch + 1) & 1;
            const int kk = (ch + 1) * 16;
            cpa16(sah + nb * BUFB, &g_Fh[aoff + kk]);
            cpa16(sal + nb * BUFB, &g_Fl[aoff + kk]);
            cpa16(sbh + nb * BUFB, &g_Bh[boff + kk]);
            cpa16(sbl + nb * BUFB, &g_Bl[boff + kk]);
            CPA_COMMIT();
        }
        uint32_t ah[2][4], al[2][4], bh[8][2], bl[8][2];
#pragma unroll
        for (int mt = 0; mt < 2; mt++) {
            int r0 = (warp_m * 32 + mt * 16 + grp) * CKS;
            ah[mt][0] = *(const uint32_t*)&sAh[buf][r0 + kq];
            ah[mt][1] = *(const uint32_t*)&sAh[buf][r0 + 8 * CKS + kq];
            ah[mt][2] = *(const uint32_t*)&sAh[buf][r0 + kq + 8];
            ah[mt][3] = *(const uint32_t*)&sAh[buf][r0 + 8 * CKS + kq + 8];
            al[mt][0] = *(const uint32_t*)&sAl[buf][r0 + kq];
            al[mt][1] = *(const uint32_t*)&sAl[buf][r0 + 8 * CKS + kq];
            al[mt][2] = *(const uint32_t*)&sAl[buf][r0 + kq + 8];
            al[mt][3] = *(const uint32_t*)&sAl[buf][r0 + 8 * CKS + kq + 8];
        }
#pragma unroll
        for (int nt = 0; nt < 8; nt++) {
            int n0 = (warp_n * 64 + nt * 8 + grp) * CKS;
            bh[nt][0] = *(const uint32_t*)&sBh[buf][n0 + kq];
            bh[nt][1] = *(const uint32_t*)&sBh[buf][n0 + kq + 8];
            bl[nt][0] = *(const uint32_t*)&sBl[buf][n0 + kq];
            bl[nt][1] = *(const uint32_t*)&sBl[buf][n0 + kq + 8];
        }
#pragma unroll
        for (int mt = 0; mt < 2; mt++)
#pragma unroll
            for (int nt = 0; nt < 8; nt++) {
                mma16816(acc[mt][nt], ah[mt], bh[nt]);
                mma16816(acc[mt][nt], ah[mt], bl[nt]);
                mma16816(acc[mt][nt], al[mt], bh[nt]);
            }
        if (ch < 31) {
            CPA_WAIT0();
            __syncthreads();
        }
    }

    // fused max-pool epilogue: max over this CTA's 128 rows, atomicMax per column
    float cmax[8][2];
#pragma unroll
    for (int nt = 0; nt < 8; nt++) {
        cmax[nt][0] = fmaxf(fmaxf(acc[0][nt][0], acc[0][nt][2]),
                            fmaxf(acc[1][nt][0], acc[1][nt][2]));
        cmax[nt][1] = fmaxf(fmaxf(acc[0][nt][1], acc[0][nt][3]),
                            fmaxf(acc[1][nt][1], acc[1][nt][3]));
    }
#pragma unroll
    for (int off = 16; off >= 4; off >>= 1)
#pragma unroll
        for (int nt = 0; nt < 8; nt++) {
            cmax[nt][0] = fmaxf(cmax[nt][0], __shfl_xor_sync(0xffffffffu, cmax[nt][0], off));
            cmax[nt][1] = fmaxf(cmax[nt][1], __shfl_xor_sync(0xffffffffu, cmax[nt][1], off));
        }
    if (lane < 4) {
        unsigned* pp = &g_pool[batch * 1024 + col0 + warp_n * 64];
#pragma unroll
        for (int nt = 0; nt < 8; nt++) {
            atomicMax(&pp[nt * 8 + lane * 2], fenc(cmax[nt][0]));
            atomicMax(&pp[nt * 8 + lane * 2 + 1], fenc(cmax[nt][1]));
        }
    }
}

// ---------------- fused MLP head ----------------
__global__ void mlp_kernel(const float* __restrict__ lin1_w,
                           const float* __restrict__ bn6_g, const float* __restrict__ bn6_b,
                           const float* __restrict__ lin2_w, const float* __restrict__ lin2_b,
                           const float* __restrict__ bn7_g, const float* __restrict__ bn7_b,
                           const float* __restrict__ lin3_w, const float* __restrict__ lin3_b,
                           float* __restrict__ out) {
    int b = blockIdx.x, t = threadIdx.x;
    __shared__ float sy[1024];
    __shared__ float s1[512];
    __shared__ float s2[256];
    for (int i = t; i < 1024; i += 256) sy[i] = fdec(g_pool[b * 1024 + i]);
    __syncthreads();
    const float r = rsqrtf(1.0f + 1e-5f);
    for (int j = t; j < 512; j += 256) {
        const float* w = lin1_w + (size_t)j * 1024;
        float acc = 0.f;
        for (int c = 0; c < 1024; c++) acc = fmaf(w[c], sy[c], acc);
        float v = fmaf(acc, bn6_g[j] * r, bn6_b[j]);
        s1[j] = (v >= 0.f) ? v : 0.01f * v;
    }
    __syncthreads();
    {
        const float* w = lin2_w + (size_t)t * 512;
        float acc = lin2_b[t];
        for (int c = 0; c < 512; c++) acc = fmaf(w[c], s1[c], acc);
        float v = fmaf(acc, bn7_g[t] * r, bn7_b[t]);
        s2[t] = (v >= 0.f) ? v : 0.01f * v;
    }
    __syncthreads();
    if (t < 40) {
        const float* w = lin3_w + (size_t)t * 256;
        float acc = lin3_b[t];
        for (int c = 0; c < 256; c++) acc = fmaf(w[c], s2[c], acc);
        out[b * 40 + t] = acc;
    }
}

extern "C" void kernel_launch(void* const* d_in, const int* in_sizes, int n_in,
                              void* d_out, int out_size) {
    const float* x       = (const float*)d_in[0];
    const float* conv1_w = (const float*)d_in[1];
    const float* conv1_b = (const float*)d_in[2];
    const float* bn1_g   = (const float*)d_in[3];
    const float* bn1_b   = (const float*)d_in[4];
    const float* conv2_w = (const float*)d_in[5];
    const float* bn2_g   = (const float*)d_in[6];
    const float* bn2_b   = (const float*)d_in[7];
    const float* conv3_w = (const float*)d_in[8];
    const float* bn3_g   = (const float*)d_in[9];
    const float* bn3_b   = (const float*)d_in[10];
    const float* conv4_w = (const float*)d_in[11];
    const float* bn4_g   = (const float*)d_in[12];
    const float* bn4_b   = (const float*)d_in[13];
    const float* conv5_w = (const float*)d_in[14];
    const float* lin1_w  = (const float*)d_in[15];
    const float* bn6_g   = (const float*)d_in[16];
    const float* bn6_b   = (const float*)d_in[17];
    const float* lin2_w  = (const float*)d_in[18];
    const float* lin2_b  = (const float*)d_in[19];
    const float* bn7_g   = (const float*)d_in[20];
    const float* bn7_b   = (const float*)d_in[21];
    const float* lin3_w  = (const float*)d_in[22];
    const float* lin3_b  = (const float*)d_in[23];
    float* out = (float*)d_out;

    prep_kernel<<<(WEND + 255) / 256, 256>>>(conv1_w, conv2_w, conv3_w, conv4_w);
    cvtB_kernel<<<1024 * 512 / 256, 256>>>(conv5_w);
    sqnorm1_kernel<<<32, 256>>>(x);

    const long sDist = (long)Npt * Npt;
    // ----- layer 1 (C=3, O=64): fp32 path -----
    gemm128_kernel<true><<<dim3(36, 1, Bsz), 256>>>(x, 0, 0, Npt, sDist);
    topk_kernel<<<Bsz * Npt / 8, 256>>>();
    gemm128_kernel<false><<<dim3(64, 1, 1), 256>>>(x, WOFF1, 1, 128, 0);
    aggregate_kernel<<<Bsz * Npt, 64>>>(64, conv1_b, bn1_g, bn1_b, 0);
    // ----- layer 2 (C=64, O=64): bf16 mma -----
    mma_gemm_kernel<4, true><<<dim3(8, 8, Bsz), 256>>>(0, 0, 0);
    topk_kernel<<<Bsz * Npt / 8, 256>>>();
    mma_gemm_kernel<4, false><<<dim3(64, 1), 256>>>(0, WOFF2, 128);
    aggregate_kernel<<<Bsz * Npt, 64>>>(64, nullptr, bn2_g, bn2_b, 64);
    // ----- layer 3 (C=64, O=128) -----
    mma_gemm_kernel<4, true><<<dim3(8, 8, Bsz), 256>>>(64, 0, 0);
    topk_kernel<<<Bsz * Npt / 8, 256>>>();
    mma_gemm_kernel<4, false><<<dim3(64, 2), 256>>>(64, WOFF3, 256);
    aggregate_kernel<<<Bsz * Npt, 128>>>(128, nullptr, bn3_g, bn3_b, 128);
    // ----- layer 4 (C=128, O=256) -----
    mma_gemm_kernel<8, true><<<dim3(8, 8, Bsz), 256>>>(128, 0, 0);
    topk_kernel<<<Bsz * Npt / 8, 256>>>();
    mma_gemm_kernel<8, false><<<dim3(64, 4), 256>>>(128, WOFF4, 512);
    aggregate_kernel<<<Bsz * Npt, 256>>>(256, nullptr, bn4_g, bn4_b, 256);

    // ----- conv5 (K=512) with fused global max-pool -----
    conv5_mma_kernel<<<dim3(64, 8), 256>>>();

    // ----- MLP head -----
    mlp_kernel<<<Bsz, 256>>>(lin1_w, bn6_g, bn6_b, lin2_w, lin2_b,
                             bn7_g, bn7_b, lin3_w, lin3_b, out);
}